// round 8
// baseline (speedup 1.0000x reference)
#include <cuda_runtime.h>
#include <math.h>
#include <stdint.h>

#define B_ 8
#define T_ 1024
#define C_ 2048
#define H_ 16
#define D_ 128
#define C3_ (3*C_)

// Scratch (device globals: allocation-free kernel_launch).
__device__ float    g_qkv[(size_t)B_*T_*C3_];   // [B*T, 3C] fp32
__device__ float    g_y  [(size_t)B_*T_*C_];    // [B*T, C]  fp32
__device__ uint32_t g_xt [(size_t)B_*T_*C_];    // x  as tf32 bits
__device__ uint32_t g_wat[(size_t)C_*C3_];      // W_attn as tf32 bits
__device__ uint32_t g_wpt[(size_t)C_*C_];       // W_proj as tf32 bits
__device__ uint32_t g_yt [(size_t)B_*T_*C_];    // y  as tf32 bits

// ===========================================================================
// helpers (base PTX only — ptxas here targets plain sm_103; no tcgen05)
// ===========================================================================
__device__ __forceinline__ uint32_t f2tf32(float f) {
    uint32_t r;
    asm("cvt.rna.tf32.f32 %0, %1;" : "=r"(r) : "f"(f));
    return r;
}
__device__ __forceinline__ uint32_t smem_u32(const void* p) {
    uint32_t a;
    asm("{ .reg .u64 t; cvta.to.shared.u64 t, %1; cvt.u32.u64 %0, t; }"
        : "=r"(a) : "l"(p));
    return a;
}
__device__ __forceinline__ void mma_tf32(float* d, const uint32_t* a,
                                         uint32_t b0, uint32_t b1) {
    asm volatile(
        "mma.sync.aligned.m16n8k8.row.col.f32.tf32.tf32.f32 "
        "{%0,%1,%2,%3}, {%4,%5,%6,%7}, {%8,%9}, {%0,%1,%2,%3};"
        : "+f"(d[0]), "+f"(d[1]), "+f"(d[2]), "+f"(d[3])
        : "r"(a[0]), "r"(a[1]), "r"(a[2]), "r"(a[3]), "r"(b0), "r"(b1));
}
__device__ __forceinline__ void cp16(uint32_t dst, const void* src) {
    asm volatile("cp.async.cg.shared.global [%0], [%1], 16;"
                 :: "r"(dst), "l"(src));
}
__device__ __forceinline__ void cp_commit() {
    asm volatile("cp.async.commit_group;" ::: "memory");
}
template <int N>
__device__ __forceinline__ void cp_wait() {
    asm volatile("cp.async.wait_group %0;" :: "n"(N) : "memory");
}

// ===========================================================================
// elementwise fp32 -> tf32-bits (RNA) conversion
// ===========================================================================
__global__ void cvt_tf32_k(const float4* __restrict__ in,
                           uint4* __restrict__ out, int n4)
{
    int i = blockIdx.x * blockDim.x + threadIdx.x;
    if (i < n4) {
        float4 v = in[i];
        out[i] = make_uint4(f2tf32(v.x), f2tf32(v.y), f2tf32(v.z), f2tf32(v.w));
    }
}

// ===========================================================================
// tf32 tensor-core GEMM with 3-stage cp.async pipeline (R6-proven, verbatim).
// ===========================================================================
#define GEMM_SMEM_CP 98304

__global__ __launch_bounds__(256, 2) void gemm_cp(
    const uint32_t* __restrict__ A, const uint32_t* __restrict__ Bm,
    const float* __restrict__ bias, float* __restrict__ Cc,
    int M, int N, int K)
{
    extern __shared__ __align__(16) uint32_t sm4[];
    const uint32_t smem_base = smem_u32(sm4);
    const int tid  = threadIdx.x;
    const int lane = tid & 31;
    const int warp = tid >> 5;
    const int wm = warp & 3, wn = warp >> 2;
    const int m0 = blockIdx.y * 128, n0 = blockIdx.x * 128;
    const int NIT = K >> 5;

    float acc[2][8][4];
#pragma unroll
    for (int i = 0; i < 2; ++i)
#pragma unroll
        for (int j = 0; j < 8; ++j)
#pragma unroll
            for (int q = 0; q < 4; ++q) acc[i][j][q] = 0.f;

    auto issue = [&](int kt, int s) {
        const int k0 = kt << 5;
        const uint32_t ab = smem_base + (uint32_t)(s * 4096) * 4;
#pragma unroll
        for (int p = 0; p < 4; ++p) {
            int i = tid + (p << 8);
            int r = i >> 3, u = i & 7;
            cp16(ab + (uint32_t)(r * 8 + (u ^ (r & 7))) * 16,
                 A + (size_t)(m0 + r) * K + k0 + (u << 2));
        }
        const uint32_t bb = smem_base + (uint32_t)(12288 + s * 4096) * 4;
#pragma unroll
        for (int p = 0; p < 4; ++p) {
            int i = tid + (p << 8);
            int k = i >> 5, n4 = (i & 31) << 2;
            cp16(bb + (uint32_t)(k * 32 + ((n4 >> 2) ^ ((k & 3) << 1))) * 16,
                 Bm + (size_t)(k0 + k) * N + n0 + n4);
        }
    };

    auto compute = [&](int s) {
        const uint32_t* as = sm4 + s * 4096;
        const uint32_t* bs = sm4 + 12288 + s * 4096;
#pragma unroll
        for (int ks = 0; ks < 4; ++ks) {
            const int kq = (ks << 3) + (lane & 3);
            uint32_t af[2][4];
#pragma unroll
            for (int i = 0; i < 2; ++i) {
                int m = wm * 32 + i * 16 + (lane >> 2);
                int sw = (m & 7) << 2;
                af[i][0] = as[m * 32 + (kq ^ sw)];
                af[i][1] = as[(m + 8) * 32 + (kq ^ sw)];
                af[i][2] = as[m * 32 + ((kq + 4) ^ sw)];
                af[i][3] = as[(m + 8) * 32 + ((kq + 4) ^ sw)];
            }
            const int ksw = (kq & 3) << 3;
#pragma unroll
            for (int j = 0; j < 8; ++j) {
                int n = wn * 64 + j * 8 + (lane >> 2);
                uint32_t b0 = bs[kq * 128 + (n ^ ksw)];
                uint32_t b1 = bs[(kq + 4) * 128 + (n ^ ksw)];
                mma_tf32(acc[0][j], af[0], b0, b1);
                mma_tf32(acc[1][j], af[1], b0, b1);
            }
        }
    };

    issue(0, 0); cp_commit();
    issue(1, 1); cp_commit();
    for (int kt = 0; kt < NIT; ++kt) {
        cp_wait<1>();
        __syncthreads();
        compute(kt % 3);
        if (kt + 2 < NIT) issue(kt + 2, (kt + 2) % 3);
        cp_commit();
    }

#pragma unroll
    for (int i = 0; i < 2; ++i) {
        const int r = m0 + wm * 32 + i * 16 + (lane >> 2);
#pragma unroll
        for (int j = 0; j < 8; ++j) {
            const int c = n0 + wn * 64 + j * 8 + ((lane & 3) << 1);
            float2 bi = *(const float2*)&bias[c];
            float2 v0 = make_float2(acc[i][j][0] + bi.x, acc[i][j][1] + bi.y);
            float2 v1 = make_float2(acc[i][j][2] + bi.x, acc[i][j][3] + bi.y);
            *(float2*)&Cc[(size_t)r * N + c]       = v0;
            *(float2*)&Cc[(size_t)(r + 8) * N + c] = v1;
        }
    }
}

// ===========================================================================
// Tensor-core flash attention (causal), tf32 mma + fp32 softmax.
// R5 structure with the KV BASE FIX: K/V rows are absolute in the sequence
// (g_qkv + b*T_*C3_ + ...), NOT offset by the Q-tile (that offset read out of
// bounds and was the R4/R5 illegal-access).
// Grid (8, B*H), 256 thr = 8 warps. Q-tile 128 (warp = 16 q-rows), KV-tile 64.
// Smem: K,V [64][132]; Q staging [128][132] (aliased); P [128][68].
// ===========================================================================
#define KV_STRIDE 132
#define P_STRIDE  68
#define OFF_K 0
#define OFF_V (64*KV_STRIDE)
#define OFF_P (2*64*KV_STRIDE)
#define ATTN_SMEM ((2*64*KV_STRIDE + 128*P_STRIDE) * 4)   // 102400 B

__global__ __launch_bounds__(256, 1) void attn_tc()
{
    extern __shared__ __align__(16) uint32_t smu[];
    uint32_t* Ks = smu + OFF_K;     // [64][132]
    uint32_t* Vs = smu + OFF_V;     // [64][132]
    uint32_t* Ps = smu + OFF_P;     // [128][68]
    uint32_t* Qs = smu;             // staging [128][132] (aliases Ks+Vs)

    const int tid  = threadIdx.x;
    const int lane = tid & 31;
    const int warp = tid >> 5;
    const int g = lane >> 2;   // 0..7
    const int t = lane & 3;    // 0..3
    const int qt = 7 - (int)blockIdx.x;          // heavy tiles first
    const int b  = blockIdx.y >> 4, h = blockIdx.y & 15;

    const float* seq = g_qkv + (size_t)b * T_ * C3_ + h * D_;  // sequence base
    const float* Qg = seq + (size_t)(qt * 128) * C3_;          // Q tile rows
    const float* Kg = seq + C_;                                 // K, absolute
    const float* Vg = seq + 2 * C_;                             // V, absolute

    // ---- stage Q (128x128 -> [128][132] tf32), lift warp's A-frags ----
#pragma unroll
    for (int p = 0; p < 16; ++p) {
        int i = tid + (p << 8);
        int r = i >> 5, c4 = (i & 31) << 2;
        float4 v = *(const float4*)(Qg + (size_t)r * C3_ + c4);
        uint4 u;
        u.x = f2tf32(v.x); u.y = f2tf32(v.y);
        u.z = f2tf32(v.z); u.w = f2tf32(v.w);
        *(uint4*)&Qs[r * KV_STRIDE + c4] = u;
    }
    __syncthreads();

    uint32_t qf[16][4];
    {
        const int m = warp * 16 + g;
#pragma unroll
        for (int ks = 0; ks < 16; ++ks) {
            const int k0 = ks * 8 + t;
            qf[ks][0] = Qs[m * KV_STRIDE + k0];
            qf[ks][1] = Qs[(m + 8) * KV_STRIDE + k0];
            qf[ks][2] = Qs[m * KV_STRIDE + k0 + 4];
            qf[ks][3] = Qs[(m + 8) * KV_STRIDE + k0 + 4];
        }
    }
    __syncthreads();

    float of[16][4];
#pragma unroll
    for (int nf = 0; nf < 16; ++nf)
#pragma unroll
        for (int q = 0; q < 4; ++q) of[nf][q] = 0.f;
    float m0h = -3.0e38f, m1h = -3.0e38f, l0 = 0.f, l1 = 0.f;

    const float scale = 0.08838834764831845f;    // 1/sqrt(128)
    const int rg0 = qt * 128 + warp * 16 + g;    // absolute q row (c0/c1; +8 c2/c3)
    const int prow = warp * 16 + g;
    const int nt  = 2 * qt + 2;

    for (int kt = 0; kt < nt; ++kt) {
        const int kv0 = kt * 64;                 // absolute kv row

        // ---- load K, V rows kv0..kv0+63 (float4, coalesced) ----
#pragma unroll
        for (int p = 0; p < 8; ++p) {
            int i = tid + (p << 8);
            int r = i >> 5, c4 = (i & 31) << 2;
            float4 v = *(const float4*)(Kg + (size_t)(kv0 + r) * C3_ + c4);
            uint4 u;
            u.x = f2tf32(v.x); u.y = f2tf32(v.y);
            u.z = f2tf32(v.z); u.w = f2tf32(v.w);
            *(uint4*)&Ks[r * KV_STRIDE + c4] = u;
        }
#pragma unroll
        for (int p = 0; p < 8; ++p) {
            int i = tid + (p << 8);
            int r = i >> 5, c4 = (i & 31) << 2;
            float4 v = *(const float4*)(Vg + (size_t)(kv0 + r) * C3_ + c4);
            uint4 u;
            u.x = f2tf32(v.x); u.y = f2tf32(v.y);
            u.z = f2tf32(v.z); u.w = f2tf32(v.w);
            *(uint4*)&Vs[r * KV_STRIDE + c4] = u;
        }
        __syncthreads();

        // ---- S = Q K^T : warp computes 16 x 64 ----
        float sc[8][4];
#pragma unroll
        for (int j = 0; j < 8; ++j)
#pragma unroll
            for (int q = 0; q < 4; ++q) sc[j][q] = 0.f;

#pragma unroll
        for (int ks = 0; ks < 16; ++ks) {
            const int kd = ks * 8 + t;
#pragma unroll
            for (int j = 0; j < 8; ++j) {
                const uint32_t* kr = &Ks[(j * 8 + g) * KV_STRIDE + kd];
                mma_tf32(sc[j], qf[ks], kr[0], kr[4]);
            }
        }

        // ---- online softmax (C-frag registers) ----
        {   // half 0: rows rg0
            float mt = -3.0e38f;
#pragma unroll
            for (int j = 0; j < 8; ++j) {
                int cg = kv0 + j * 8 + 2 * t;
                float v0 = sc[j][0] * scale; if (cg > rg0)     v0 = -1.0e9f;
                float v1 = sc[j][1] * scale; if (cg + 1 > rg0) v1 = -1.0e9f;
                sc[j][0] = v0; sc[j][1] = v1;
                mt = fmaxf(mt, fmaxf(v0, v1));
            }
            mt = fmaxf(mt, __shfl_xor_sync(~0u, mt, 1));
            mt = fmaxf(mt, __shfl_xor_sync(~0u, mt, 2));
            float mn = fmaxf(m0h, mt);
            float sum = 0.f;
#pragma unroll
            for (int j = 0; j < 8; ++j) {
                float p0 = __expf(sc[j][0] - mn);
                float p1 = __expf(sc[j][1] - mn);
                sum += p0 + p1;
                sc[j][0] = p0; sc[j][1] = p1;
            }
            sum += __shfl_xor_sync(~0u, sum, 1);
            sum += __shfl_xor_sync(~0u, sum, 2);
            float corr = __expf(m0h - mn);
            l0 = l0 * corr + sum; m0h = mn;
#pragma unroll
            for (int nf = 0; nf < 16; ++nf) { of[nf][0] *= corr; of[nf][1] *= corr; }
        }
        {   // half 1: rows rg0+8
            float mt = -3.0e38f;
#pragma unroll
            for (int j = 0; j < 8; ++j) {
                int cg = kv0 + j * 8 + 2 * t;
                float v0 = sc[j][2] * scale; if (cg > rg0 + 8)     v0 = -1.0e9f;
                float v1 = sc[j][3] * scale; if (cg + 1 > rg0 + 8) v1 = -1.0e9f;
                sc[j][2] = v0; sc[j][3] = v1;
                mt = fmaxf(mt, fmaxf(v0, v1));
            }
            mt = fmaxf(mt, __shfl_xor_sync(~0u, mt, 1));
            mt = fmaxf(mt, __shfl_xor_sync(~0u, mt, 2));
            float mn = fmaxf(m1h, mt);
            float sum = 0.f;
#pragma unroll
            for (int j = 0; j < 8; ++j) {
                float p0 = __expf(sc[j][2] - mn);
                float p1 = __expf(sc[j][3] - mn);
                sum += p0 + p1;
                sc[j][2] = p0; sc[j][3] = p1;
            }
            sum += __shfl_xor_sync(~0u, sum, 1);
            sum += __shfl_xor_sync(~0u, sum, 2);
            float corr = __expf(m1h - mn);
            l1 = l1 * corr + sum; m1h = mn;
#pragma unroll
            for (int nf = 0; nf < 16; ++nf) { of[nf][2] *= corr; of[nf][3] *= corr; }
        }

        // ---- P: C-frags -> warp-private smem rows -> A-frags ----
#pragma unroll
        for (int j = 0; j < 8; ++j) {
            uint2 u0 = make_uint2(f2tf32(sc[j][0]), f2tf32(sc[j][1]));
            uint2 u1 = make_uint2(f2tf32(sc[j][2]), f2tf32(sc[j][3]));
            *(uint2*)&Ps[prow * P_STRIDE + j * 8 + 2 * t]       = u0;
            *(uint2*)&Ps[(prow + 8) * P_STRIDE + j * 8 + 2 * t] = u1;
        }
        __syncwarp();

        uint32_t pa[8][4];
#pragma unroll
        for (int ks2 = 0; ks2 < 8; ++ks2) {
            const int k0 = ks2 * 8 + t;
            pa[ks2][0] = Ps[prow * P_STRIDE + k0];
            pa[ks2][1] = Ps[(prow + 8) * P_STRIDE + k0];
            pa[ks2][2] = Ps[prow * P_STRIDE + k0 + 4];
            pa[ks2][3] = Ps[(prow + 8) * P_STRIDE + k0 + 4];
        }

        // ---- O += P V : warp 16 x 128 ----
#pragma unroll
        for (int ks2 = 0; ks2 < 8; ++ks2) {
            const int kv = ks2 * 8 + t;
#pragma unroll
            for (int nf = 0; nf < 16; ++nf) {
                uint32_t b0 = Vs[kv * KV_STRIDE + nf * 8 + g];
                uint32_t b1 = Vs[(kv + 4) * KV_STRIDE + nf * 8 + g];
                mma_tf32(of[nf], pa[ks2], b0, b1);
            }
        }
        __syncthreads();   // all K/V reads done before next tile's stores
    }

    // ---- epilogue: O/l -> g_y with head merge ----
    const float inv0 = 1.0f / l0, inv1 = 1.0f / l1;
    const size_t r0 = (size_t)(b*T_ + qt*128 + warp*16 + g) * C_ + h*D_;
#pragma unroll
    for (int nf = 0; nf < 16; ++nf) {
        const int col = nf * 8 + 2 * t;
        *(float2*)&g_y[r0 + col] =
            make_float2(of[nf][0] * inv0, of[nf][1] * inv0);
        *(float2*)&g_y[r0 + (size_t)8 * C_ + col] =
            make_float2(of[nf][2] * inv1, of[nf][3] * inv1);
    }
}

// ---------------------------------------------------------------------------
extern "C" void kernel_launch(void* const* d_in, const int* in_sizes, int n_in,
                              void* d_out, int out_size)
{
    const float* x      = (const float*)d_in[0];
    const float* W_attn = (const float*)d_in[1];
    const float* b_attn = (const float*)d_in[2];
    const float* W_proj = (const float*)d_in[3];
    const float* b_proj = (const float*)d_in[4];
    float* out = (float*)d_out;

    float *qkv_ptr = nullptr, *y_ptr = nullptr;
    uint32_t *xt = nullptr, *wat = nullptr, *wpt = nullptr, *yt = nullptr;
    cudaGetSymbolAddress((void**)&qkv_ptr, g_qkv);
    cudaGetSymbolAddress((void**)&y_ptr,   g_y);
    cudaGetSymbolAddress((void**)&xt,  g_xt);
    cudaGetSymbolAddress((void**)&wat, g_wat);
    cudaGetSymbolAddress((void**)&wpt, g_wpt);
    cudaGetSymbolAddress((void**)&yt,  g_yt);

    cudaFuncSetAttribute(gemm_cp,
                         cudaFuncAttributeMaxDynamicSharedMemorySize, GEMM_SMEM_CP);
    cudaFuncSetAttribute(attn_tc,
                         cudaFuncAttributeMaxDynamicSharedMemorySize, ATTN_SMEM);

    // 0) one-shot tf32 conversions of GEMM inputs
    int n4;
    n4 = (B_*T_*C_) / 4;
    cvt_tf32_k<<<(n4 + 255) / 256, 256>>>((const float4*)x, (uint4*)xt, n4);
    n4 = (C_*C3_) / 4;
    cvt_tf32_k<<<(n4 + 255) / 256, 256>>>((const float4*)W_attn, (uint4*)wat, n4);
    n4 = (C_*C_) / 4;
    cvt_tf32_k<<<(n4 + 255) / 256, 256>>>((const float4*)W_proj, (uint4*)wpt, n4);

    // 1) qkv = x @ W_attn + b_attn          [8192, 6144]
    gemm_cp<<<dim3(C3_/128, (B_*T_)/128), 256, GEMM_SMEM_CP>>>(
        xt, wat, b_attn, qkv_ptr, B_*T_, C3_, C_);

    // 2) causal flash attention -> g_y      [8192, 2048]
    attn_tc<<<dim3(T_/128, B_*H_), 256, ATTN_SMEM>>>();

    // 2b) y -> tf32 bits
    n4 = (B_*T_*C_) / 4;
    cvt_tf32_k<<<(n4 + 255) / 256, 256>>>((const float4*)y_ptr, (uint4*)yt, n4);

    // 3) out = y @ W_proj + b_proj          [8192, 2048]
    gemm_cp<<<dim3(C_/128, (B_*T_)/128), 256, GEMM_SMEM_CP>>>(
        yt, wpt, b_proj, out, B_*T_, C_, C_);
}

// round 9
// speedup vs baseline: 1.5752x; 1.5752x over previous
#include <cuda_runtime.h>
#include <math.h>
#include <stdint.h>

#define B_ 8
#define T_ 1024
#define C_ 2048
#define H_ 16
#define D_ 128
#define C3_ (3*C_)

// Scratch (device globals: allocation-free kernel_launch).
__device__ uint32_t g_qkvt[(size_t)B_*T_*C3_];  // qkv as tf32 bits
__device__ uint32_t g_xt [(size_t)B_*T_*C_];    // x  as tf32 bits
__device__ uint32_t g_wat[(size_t)C_*C3_];      // W_attn as tf32 bits
__device__ uint32_t g_wpt[(size_t)C_*C_];       // W_proj as tf32 bits
__device__ uint32_t g_yt [(size_t)B_*T_*C_];    // y  as tf32 bits

// ===========================================================================
// helpers (base PTX only — ptxas here targets plain sm_103; no tcgen05)
// ===========================================================================
__device__ __forceinline__ uint32_t f2tf32(float f) {
    uint32_t r;
    asm("cvt.rna.tf32.f32 %0, %1;" : "=r"(r) : "f"(f));
    return r;
}
__device__ __forceinline__ uint32_t smem_u32(const void* p) {
    uint32_t a;
    asm("{ .reg .u64 t; cvta.to.shared.u64 t, %1; cvt.u32.u64 %0, t; }"
        : "=r"(a) : "l"(p));
    return a;
}
__device__ __forceinline__ void mma_tf32(float* d, const uint32_t* a,
                                         uint32_t b0, uint32_t b1) {
    asm volatile(
        "mma.sync.aligned.m16n8k8.row.col.f32.tf32.tf32.f32 "
        "{%0,%1,%2,%3}, {%4,%5,%6,%7}, {%8,%9}, {%0,%1,%2,%3};"
        : "+f"(d[0]), "+f"(d[1]), "+f"(d[2]), "+f"(d[3])
        : "r"(a[0]), "r"(a[1]), "r"(a[2]), "r"(a[3]), "r"(b0), "r"(b1));
}
__device__ __forceinline__ void cp16(uint32_t dst, const void* src) {
    asm volatile("cp.async.cg.shared.global [%0], [%1], 16;"
                 :: "r"(dst), "l"(src));
}
__device__ __forceinline__ void cp_commit() {
    asm volatile("cp.async.commit_group;" ::: "memory");
}
template <int N>
__device__ __forceinline__ void cp_wait() {
    asm volatile("cp.async.wait_group %0;" :: "n"(N) : "memory");
}

// ===========================================================================
// elementwise fp32 -> tf32-bits (RNA) conversion
// ===========================================================================
__global__ void cvt_tf32_k(const float4* __restrict__ in,
                           uint4* __restrict__ out, int n4)
{
    int i = blockIdx.x * blockDim.x + threadIdx.x;
    if (i < n4) {
        float4 v = in[i];
        out[i] = make_uint4(f2tf32(v.x), f2tf32(v.y), f2tf32(v.z), f2tf32(v.w));
    }
}

// ===========================================================================
// tf32 tensor-core GEMM, 3-stage cp.async pipeline (R6-proven mainloop).
// TF32OUT: store C as tf32 bits (RNA) instead of fp32.
// ===========================================================================
#define GEMM_SMEM_CP 98304

template <bool TF32OUT>
__global__ __launch_bounds__(256, 2) void gemm_cp(
    const uint32_t* __restrict__ A, const uint32_t* __restrict__ Bm,
    const float* __restrict__ bias, void* __restrict__ Cout,
    int M, int N, int K)
{
    extern __shared__ __align__(16) uint32_t sm4[];
    const uint32_t smem_base = smem_u32(sm4);
    const int tid  = threadIdx.x;
    const int lane = tid & 31;
    const int warp = tid >> 5;
    const int wm = warp & 3, wn = warp >> 2;
    const int m0 = blockIdx.y * 128, n0 = blockIdx.x * 128;
    const int NIT = K >> 5;

    float acc[2][8][4];
#pragma unroll
    for (int i = 0; i < 2; ++i)
#pragma unroll
        for (int j = 0; j < 8; ++j)
#pragma unroll
            for (int q = 0; q < 4; ++q) acc[i][j][q] = 0.f;

    auto issue = [&](int kt, int s) {
        const int k0 = kt << 5;
        const uint32_t ab = smem_base + (uint32_t)(s * 4096) * 4;
#pragma unroll
        for (int p = 0; p < 4; ++p) {
            int i = tid + (p << 8);
            int r = i >> 3, u = i & 7;
            cp16(ab + (uint32_t)(r * 8 + (u ^ (r & 7))) * 16,
                 A + (size_t)(m0 + r) * K + k0 + (u << 2));
        }
        const uint32_t bb = smem_base + (uint32_t)(12288 + s * 4096) * 4;
#pragma unroll
        for (int p = 0; p < 4; ++p) {
            int i = tid + (p << 8);
            int k = i >> 5, n4 = (i & 31) << 2;
            cp16(bb + (uint32_t)(k * 32 + ((n4 >> 2) ^ ((k & 3) << 1))) * 16,
                 Bm + (size_t)(k0 + k) * N + n0 + n4);
        }
    };

    auto compute = [&](int s) {
        const uint32_t* as = sm4 + s * 4096;
        const uint32_t* bs = sm4 + 12288 + s * 4096;
#pragma unroll
        for (int ks = 0; ks < 4; ++ks) {
            const int kq = (ks << 3) + (lane & 3);
            uint32_t af[2][4];
#pragma unroll
            for (int i = 0; i < 2; ++i) {
                int m = wm * 32 + i * 16 + (lane >> 2);
                int sw = (m & 7) << 2;
                af[i][0] = as[m * 32 + (kq ^ sw)];
                af[i][1] = as[(m + 8) * 32 + (kq ^ sw)];
                af[i][2] = as[m * 32 + ((kq + 4) ^ sw)];
                af[i][3] = as[(m + 8) * 32 + ((kq + 4) ^ sw)];
            }
            const int ksw = (kq & 3) << 3;
#pragma unroll
            for (int j = 0; j < 8; ++j) {
                int n = wn * 64 + j * 8 + (lane >> 2);
                uint32_t b0 = bs[kq * 128 + (n ^ ksw)];
                uint32_t b1 = bs[(kq + 4) * 128 + (n ^ ksw)];
                mma_tf32(acc[0][j], af[0], b0, b1);
                mma_tf32(acc[1][j], af[1], b0, b1);
            }
        }
    };

    issue(0, 0); cp_commit();
    issue(1, 1); cp_commit();
    for (int kt = 0; kt < NIT; ++kt) {
        cp_wait<1>();
        __syncthreads();
        compute(kt % 3);
        if (kt + 2 < NIT) issue(kt + 2, (kt + 2) % 3);
        cp_commit();
    }

#pragma unroll
    for (int i = 0; i < 2; ++i) {
        const int r = m0 + wm * 32 + i * 16 + (lane >> 2);
#pragma unroll
        for (int j = 0; j < 8; ++j) {
            const int c = n0 + wn * 64 + j * 8 + ((lane & 3) << 1);
            float2 bi = *(const float2*)&bias[c];
            float v00 = acc[i][j][0] + bi.x, v01 = acc[i][j][1] + bi.y;
            float v10 = acc[i][j][2] + bi.x, v11 = acc[i][j][3] + bi.y;
            if (TF32OUT) {
                uint32_t* Cc = (uint32_t*)Cout;
                *(uint2*)&Cc[(size_t)r * N + c] = make_uint2(f2tf32(v00), f2tf32(v01));
                *(uint2*)&Cc[(size_t)(r + 8) * N + c] = make_uint2(f2tf32(v10), f2tf32(v11));
            } else {
                float* Cc = (float*)Cout;
                *(float2*)&Cc[(size_t)r * N + c]       = make_float2(v00, v01);
                *(float2*)&Cc[(size_t)(r + 8) * N + c] = make_float2(v10, v11);
            }
        }
    }
}

// ===========================================================================
// Tensor-core flash attention (causal), tf32 mma + fp32 softmax.
// R7-proven compute structure + cp.async DOUBLE-BUFFERED K/V prefetch:
//   wait<0> -> sync -> issue(kt+1, other buf) -> compute(kt)
// so tile kt+1's copy overlaps tile kt's mma/softmax.
// Inputs already tf32 bits (g_qkvt); output y written as tf32 bits (g_yt).
// Smem (words): KB0=0, KB1=8448, VB0=16896, VB1=25344, P=33792..38143.
// Q staging reuses words 0..16895 before the first issue.
// ===========================================================================
#define KV_STRIDE 132
#define P_STRIDE  68
#define OFF_VB 16896
#define OFF_P  33792
#define ATTN_SMEM ((OFF_P + 128*P_STRIDE) * 4)   // 152,576 B

__global__ __launch_bounds__(256, 1) void attn_tc()
{
    extern __shared__ __align__(16) uint32_t smu[];
    const uint32_t smem_base = smem_u32(smu);
    uint32_t* Ps = smu + OFF_P;     // [128][68]
    uint32_t* Qs = smu;             // staging [128][132] (words 0..16895)

    const int tid  = threadIdx.x;
    const int lane = tid & 31;
    const int warp = tid >> 5;
    const int g = lane >> 2;   // 0..7
    const int t = lane & 3;    // 0..3
    const int qt = 7 - (int)blockIdx.x;          // heavy tiles first
    const int b  = blockIdx.y >> 4, h = blockIdx.y & 15;

    const uint32_t* seq = g_qkvt + (size_t)b * T_ * C3_ + h * D_;
    const uint32_t* Qg = seq + (size_t)(qt * 128) * C3_;
    const uint32_t* Kg = seq + C_;
    const uint32_t* Vg = seq + 2 * C_;

    // ---- stage Q [128][132] (already tf32), lift warp's A-frags ----
#pragma unroll
    for (int p = 0; p < 16; ++p) {
        int i = tid + (p << 8);
        int r = i >> 5, c4 = (i & 31) << 2;
        *(uint4*)&Qs[r * KV_STRIDE + c4] =
            *(const uint4*)(Qg + (size_t)r * C3_ + c4);
    }
    __syncthreads();

    uint32_t qf[16][4];
    {
        const int m = warp * 16 + g;
#pragma unroll
        for (int ks = 0; ks < 16; ++ks) {
            const int k0 = ks * 8 + t;
            qf[ks][0] = Qs[m * KV_STRIDE + k0];
            qf[ks][1] = Qs[(m + 8) * KV_STRIDE + k0];
            qf[ks][2] = Qs[m * KV_STRIDE + k0 + 4];
            qf[ks][3] = Qs[(m + 8) * KV_STRIDE + k0 + 4];
        }
    }
    __syncthreads();   // frags lifted before issue(0) overwrites staging

    float of[16][4];
#pragma unroll
    for (int nf = 0; nf < 16; ++nf)
#pragma unroll
        for (int q = 0; q < 4; ++q) of[nf][q] = 0.f;
    float m0h = -3.0e38f, m1h = -3.0e38f, l0 = 0.f, l1 = 0.f;

    const float scale = 0.08838834764831845f;    // 1/sqrt(128)
    const int rg0 = qt * 128 + warp * 16 + g;
    const int prow = warp * 16 + g;
    const int nt  = 2 * qt + 2;

    auto issueKV = [&](int kt, int s) {
        const int kv0 = kt * 64;
        const uint32_t kb = smem_base + (uint32_t)(s * 8448) * 4;
        const uint32_t vb = smem_base + (uint32_t)(OFF_VB + s * 8448) * 4;
#pragma unroll
        for (int p = 0; p < 8; ++p) {
            int i = tid + (p << 8);
            int r = i >> 5, c4 = (i & 31) << 2;
            cp16(kb + (uint32_t)(r * KV_STRIDE + c4) * 4,
                 Kg + (size_t)(kv0 + r) * C3_ + c4);
            cp16(vb + (uint32_t)(r * KV_STRIDE + c4) * 4,
                 Vg + (size_t)(kv0 + r) * C3_ + c4);
        }
    };

    issueKV(0, 0); cp_commit();

    for (int kt = 0; kt < nt; ++kt) {
        cp_wait<0>();
        __syncthreads();   // tile kt resident; all warps past compute(kt-1)
        if (kt + 1 < nt) { issueKV(kt + 1, (kt + 1) & 1); cp_commit(); }

        const uint32_t* Ks = smu + (kt & 1) * 8448;
        const uint32_t* Vs = smu + OFF_VB + (kt & 1) * 8448;
        const int kv0 = kt * 64;

        // ---- S = Q K^T : warp computes 16 x 64 ----
        float sc[8][4];
#pragma unroll
        for (int j = 0; j < 8; ++j)
#pragma unroll
            for (int q = 0; q < 4; ++q) sc[j][q] = 0.f;

#pragma unroll
        for (int ks = 0; ks < 16; ++ks) {
            const int kd = ks * 8 + t;
#pragma unroll
            for (int j = 0; j < 8; ++j) {
                const uint32_t* kr = &Ks[(j * 8 + g) * KV_STRIDE + kd];
                mma_tf32(sc[j], qf[ks], kr[0], kr[4]);
            }
        }

        // ---- online softmax (C-frag registers) ----
        {   // half 0: rows rg0
            float mt = -3.0e38f;
#pragma unroll
            for (int j = 0; j < 8; ++j) {
                int cg = kv0 + j * 8 + 2 * t;
                float v0 = sc[j][0] * scale; if (cg > rg0)     v0 = -1.0e9f;
                float v1 = sc[j][1] * scale; if (cg + 1 > rg0) v1 = -1.0e9f;
                sc[j][0] = v0; sc[j][1] = v1;
                mt = fmaxf(mt, fmaxf(v0, v1));
            }
            mt = fmaxf(mt, __shfl_xor_sync(~0u, mt, 1));
            mt = fmaxf(mt, __shfl_xor_sync(~0u, mt, 2));
            float mn = fmaxf(m0h, mt);
            float sum = 0.f;
#pragma unroll
            for (int j = 0; j < 8; ++j) {
                float p0 = __expf(sc[j][0] - mn);
                float p1 = __expf(sc[j][1] - mn);
                sum += p0 + p1;
                sc[j][0] = p0; sc[j][1] = p1;
            }
            sum += __shfl_xor_sync(~0u, sum, 1);
            sum += __shfl_xor_sync(~0u, sum, 2);
            float corr = __expf(m0h - mn);
            l0 = l0 * corr + sum; m0h = mn;
#pragma unroll
            for (int nf = 0; nf < 16; ++nf) { of[nf][0] *= corr; of[nf][1] *= corr; }
        }
        {   // half 1: rows rg0+8
            float mt = -3.0e38f;
#pragma unroll
            for (int j = 0; j < 8; ++j) {
                int cg = kv0 + j * 8 + 2 * t;
                float v0 = sc[j][2] * scale; if (cg > rg0 + 8)     v0 = -1.0e9f;
                float v1 = sc[j][3] * scale; if (cg + 1 > rg0 + 8) v1 = -1.0e9f;
                sc[j][2] = v0; sc[j][3] = v1;
                mt = fmaxf(mt, fmaxf(v0, v1));
            }
            mt = fmaxf(mt, __shfl_xor_sync(~0u, mt, 1));
            mt = fmaxf(mt, __shfl_xor_sync(~0u, mt, 2));
            float mn = fmaxf(m1h, mt);
            float sum = 0.f;
#pragma unroll
            for (int j = 0; j < 8; ++j) {
                float p0 = __expf(sc[j][2] - mn);
                float p1 = __expf(sc[j][3] - mn);
                sum += p0 + p1;
                sc[j][2] = p0; sc[j][3] = p1;
            }
            sum += __shfl_xor_sync(~0u, sum, 1);
            sum += __shfl_xor_sync(~0u, sum, 2);
            float corr = __expf(m1h - mn);
            l1 = l1 * corr + sum; m1h = mn;
#pragma unroll
            for (int nf = 0; nf < 16; ++nf) { of[nf][2] *= corr; of[nf][3] *= corr; }
        }

        // ---- P: C-frags -> warp-private smem rows -> A-frags ----
#pragma unroll
        for (int j = 0; j < 8; ++j) {
            uint2 u0 = make_uint2(f2tf32(sc[j][0]), f2tf32(sc[j][1]));
            uint2 u1 = make_uint2(f2tf32(sc[j][2]), f2tf32(sc[j][3]));
            *(uint2*)&Ps[prow * P_STRIDE + j * 8 + 2 * t]       = u0;
            *(uint2*)&Ps[(prow + 8) * P_STRIDE + j * 8 + 2 * t] = u1;
        }
        __syncwarp();

        uint32_t pa[8][4];
#pragma unroll
        for (int ks2 = 0; ks2 < 8; ++ks2) {
            const int k0 = ks2 * 8 + t;
            pa[ks2][0] = Ps[prow * P_STRIDE + k0];
            pa[ks2][1] = Ps[(prow + 8) * P_STRIDE + k0];
            pa[ks2][2] = Ps[prow * P_STRIDE + k0 + 4];
            pa[ks2][3] = Ps[(prow + 8) * P_STRIDE + k0 + 4];
        }

        // ---- O += P V : warp 16 x 128 ----
#pragma unroll
        for (int ks2 = 0; ks2 < 8; ++ks2) {
            const int kv = ks2 * 8 + t;
#pragma unroll
            for (int nf = 0; nf < 16; ++nf) {
                uint32_t b0 = Vs[kv * KV_STRIDE + nf * 8 + g];
                uint32_t b1 = Vs[(kv + 4) * KV_STRIDE + nf * 8 + g];
                mma_tf32(of[nf], pa[ks2], b0, b1);
            }
        }
    }

    // ---- epilogue: O/l -> g_yt (tf32 bits) with head merge ----
    const float inv0 = 1.0f / l0, inv1 = 1.0f / l1;
    const size_t r0 = (size_t)(b*T_ + qt*128 + warp*16 + g) * C_ + h*D_;
#pragma unroll
    for (int nf = 0; nf < 16; ++nf) {
        const int col = nf * 8 + 2 * t;
        *(uint2*)&g_yt[r0 + col] =
            make_uint2(f2tf32(of[nf][0] * inv0), f2tf32(of[nf][1] * inv0));
        *(uint2*)&g_yt[r0 + (size_t)8 * C_ + col] =
            make_uint2(f2tf32(of[nf][2] * inv1), f2tf32(of[nf][3] * inv1));
    }
}

// ---------------------------------------------------------------------------
extern "C" void kernel_launch(void* const* d_in, const int* in_sizes, int n_in,
                              void* d_out, int out_size)
{
    const float* x      = (const float*)d_in[0];
    const float* W_attn = (const float*)d_in[1];
    const float* b_attn = (const float*)d_in[2];
    const float* W_proj = (const float*)d_in[3];
    const float* b_proj = (const float*)d_in[4];
    float* out = (float*)d_out;

    uint32_t *qkvt = nullptr, *xt = nullptr, *wat = nullptr,
             *wpt = nullptr, *yt = nullptr;
    cudaGetSymbolAddress((void**)&qkvt, g_qkvt);
    cudaGetSymbolAddress((void**)&xt,  g_xt);
    cudaGetSymbolAddress((void**)&wat, g_wat);
    cudaGetSymbolAddress((void**)&wpt, g_wpt);
    cudaGetSymbolAddress((void**)&yt,  g_yt);

    cudaFuncSetAttribute(gemm_cp<true>,
                         cudaFuncAttributeMaxDynamicSharedMemorySize, GEMM_SMEM_CP);
    cudaFuncSetAttribute(gemm_cp<false>,
                         cudaFuncAttributeMaxDynamicSharedMemorySize, GEMM_SMEM_CP);
    cudaFuncSetAttribute(attn_tc,
                         cudaFuncAttributeMaxDynamicSharedMemorySize, ATTN_SMEM);

    // 0) one-shot tf32 conversions of external inputs
    int n4;
    n4 = (B_*T_*C_) / 4;
    cvt_tf32_k<<<(n4 + 255) / 256, 256>>>((const float4*)x, (uint4*)xt, n4);
    n4 = (C_*C3_) / 4;
    cvt_tf32_k<<<(n4 + 255) / 256, 256>>>((const float4*)W_attn, (uint4*)wat, n4);
    n4 = (C_*C_) / 4;
    cvt_tf32_k<<<(n4 + 255) / 256, 256>>>((const float4*)W_proj, (uint4*)wpt, n4);

    // 1) qkv = x @ W_attn + b_attn -> tf32 bits   [8192, 6144]
    gemm_cp<true><<<dim3(C3_/128, (B_*T_)/128), 256, GEMM_SMEM_CP>>>(
        xt, wat, b_attn, qkvt, B_*T_, C3_, C_);

    // 2) causal flash attention -> g_yt (tf32)    [8192, 2048]
    attn_tc<<<dim3(T_/128, B_*H_), 256, ATTN_SMEM>>>();

    // 3) out = y @ W_proj + b_proj                [8192, 2048]
    gemm_cp<false><<<dim3(C_/128, (B_*T_)/128), 256, GEMM_SMEM_CP>>>(
        yt, wpt, b_proj, out, B_*T_, C_, C_);
}

// round 11
// speedup vs baseline: 1.6719x; 1.0614x over previous
#include <cuda_runtime.h>
#include <math.h>
#include <stdint.h>

#define B_ 8
#define T_ 1024
#define C_ 2048
#define H_ 16
#define D_ 128
#define C3_ (3*C_)

// Scratch (device globals: allocation-free kernel_launch).
__device__ uint32_t g_qkvt[(size_t)B_*T_*C3_];  // qkv as tf32 bits
__device__ uint32_t g_xt [(size_t)B_*T_*C_];    // x  as tf32 bits
__device__ uint32_t g_wat[(size_t)C_*C3_];      // W_attn^T as tf32 bits [3C][C]
__device__ uint32_t g_wpt[(size_t)C_*C_];       // W_proj^T as tf32 bits [C][C]
__device__ uint32_t g_yt [(size_t)B_*T_*C_];    // y  as tf32 bits

// ===========================================================================
// helpers (base PTX only — ptxas here targets plain sm_103; no tcgen05)
// ===========================================================================
__device__ __forceinline__ uint32_t f2tf32(float f) {
    uint32_t r;
    asm("cvt.rna.tf32.f32 %0, %1;" : "=r"(r) : "f"(f));
    return r;
}
__device__ __forceinline__ uint32_t smem_u32(const void* p) {
    uint32_t a;
    asm("{ .reg .u64 t; cvta.to.shared.u64 t, %1; cvt.u32.u64 %0, t; }"
        : "=r"(a) : "l"(p));
    return a;
}
__device__ __forceinline__ void mma_tf32(float* d, const uint32_t* a,
                                         uint32_t b0, uint32_t b1) {
    asm volatile(
        "mma.sync.aligned.m16n8k8.row.col.f32.tf32.tf32.f32 "
        "{%0,%1,%2,%3}, {%4,%5,%6,%7}, {%8,%9}, {%0,%1,%2,%3};"
        : "+f"(d[0]), "+f"(d[1]), "+f"(d[2]), "+f"(d[3])
        : "r"(a[0]), "r"(a[1]), "r"(a[2]), "r"(a[3]), "r"(b0), "r"(b1));
}
__device__ __forceinline__ void ldsm4(uint32_t* r, uint32_t addr) {
    asm volatile("ldmatrix.sync.aligned.m8n8.x4.shared.b16 {%0,%1,%2,%3}, [%4];"
        : "=r"(r[0]), "=r"(r[1]), "=r"(r[2]), "=r"(r[3]) : "r"(addr));
}
__device__ __forceinline__ void cp16(uint32_t dst, const void* src) {
    asm volatile("cp.async.cg.shared.global [%0], [%1], 16;"
                 :: "r"(dst), "l"(src));
}
__device__ __forceinline__ void cp_commit() {
    asm volatile("cp.async.commit_group;" ::: "memory");
}
template <int N>
__device__ __forceinline__ void cp_wait() {
    asm volatile("cp.async.wait_group %0;" :: "n"(N) : "memory");
}

// ===========================================================================
// elementwise fp32 -> tf32-bits (RNA)
// ===========================================================================
__global__ void cvt_tf32_k(const float4* __restrict__ in,
                           uint4* __restrict__ out, int n4)
{
    int i = blockIdx.x * blockDim.x + threadIdx.x;
    if (i < n4) {
        float4 v = in[i];
        out[i] = make_uint4(f2tf32(v.x), f2tf32(v.y), f2tf32(v.z), f2tf32(v.w));
    }
}

// ===========================================================================
// transpose + convert: in [Kd][Nd] fp32 -> out [Nd][Kd] tf32 bits
// 32x32 tiles, 256 threads (32x8), smem pad 33 (conflict-free both phases).
// ===========================================================================
__global__ void transpose_cvt(const float* __restrict__ in,
                              uint32_t* __restrict__ out, int Kd, int Nd)
{
    __shared__ float tile[32][33];
    const int k0 = blockIdx.y * 32, n0 = blockIdx.x * 32;
    const int tx = threadIdx.x & 31, ty = threadIdx.x >> 5;
#pragma unroll
    for (int p = 0; p < 4; ++p) {
        int k = ty + p * 8;
        tile[k][tx] = in[(size_t)(k0 + k) * Nd + n0 + tx];
    }
    __syncthreads();
#pragma unroll
    for (int p = 0; p < 4; ++p) {
        int n = ty + p * 8;
        out[(size_t)(n0 + n) * Kd + k0 + tx] = f2tf32(tile[tx][n]);
    }
}

// ===========================================================================
// tf32 tensor-core GEMM, 3-stage cp.async pipeline + ldmatrix fragments.
// C[M,N] = A[M,K] @ BT[N,K]^T + bias[N]; A,BT pre-converted tf32 bits.
// CTA 128x128, BK=32, 256 thr (8 warps 4x2), warp tile 32x64.
// BOTH stages use layout: uint4 unit (row r, 16B unit u) at r*8 + (u^(r&7)).
// Fragments loaded with ldmatrix.x4 (6 per warp per ks-step-pair... 6/chunk-step):
//   per ks: A 2x ldsm4, B 4x ldsm4, 16 mma.
// 3 stages x (16KB A + 16KB B) = 96KB; 2 CTAs/SM.
// ===========================================================================
#define GEMM_SMEM_CP 98304

template <bool TF32OUT>
__global__ __launch_bounds__(256, 2) void gemm_cp(
    const uint32_t* __restrict__ A, const uint32_t* __restrict__ BT,
    const float* __restrict__ bias, void* __restrict__ Cout,
    int M, int N, int K)
{
    extern __shared__ __align__(16) uint32_t sm4[];
    const uint32_t smem_base = smem_u32(sm4);
    const int tid  = threadIdx.x;
    const int lane = tid & 31;
    const int warp = tid >> 5;
    const int wm = warp & 3, wn = warp >> 2;
    const int m0 = blockIdx.y * 128, n0 = blockIdx.x * 128;
    const int NIT = K >> 5;

    float acc[2][8][4];
#pragma unroll
    for (int i = 0; i < 2; ++i)
#pragma unroll
        for (int j = 0; j < 8; ++j)
#pragma unroll
            for (int q = 0; q < 4; ++q) acc[i][j][q] = 0.f;

    auto issue = [&](int kt, int s) {
        const int k0 = kt << 5;
        const uint32_t ab = smem_base + (uint32_t)(s * 4096) * 4;
#pragma unroll
        for (int p = 0; p < 4; ++p) {
            int i = tid + (p << 8);
            int r = i >> 3, u = i & 7;
            cp16(ab + (uint32_t)(r * 8 + (u ^ (r & 7))) * 16,
                 A + (size_t)(m0 + r) * K + k0 + (u << 2));
        }
        const uint32_t bb = smem_base + (uint32_t)(12288 + s * 4096) * 4;
#pragma unroll
        for (int p = 0; p < 4; ++p) {
            int i = tid + (p << 8);
            int r = i >> 3, u = i & 7;
            cp16(bb + (uint32_t)(r * 8 + (u ^ (r & 7))) * 16,
                 BT + (size_t)(n0 + r) * K + k0 + (u << 2));
        }
    };

    // ldmatrix lane geometry (constant per thread)
    const int localA = lane & 7;
    const int matA   = lane >> 3;          // 0..3: (m-half, k-quad-half)
    const int rowA0  = wm * 32 + (matA & 1) * 8 + localA;       // i=0 tile
    const int qselA  = matA >> 1;
    const int localB = lane & 7;
    const int pairB  = lane >> 4;          // j within pair
    const int matB   = (lane >> 3) & 1;    // k-quad half
    // rowB for j-pair jj: wn*64 + (2*jj + pairB)*8 + localB

    auto compute = [&](int s) {
        const uint32_t as_b = smem_base + (uint32_t)(s * 4096) * 4;
        const uint32_t bs_b = smem_base + (uint32_t)(12288 + s * 4096) * 4;
#pragma unroll
        for (int ks = 0; ks < 4; ++ks) {
            uint32_t af[2][4];
#pragma unroll
            for (int i = 0; i < 2; ++i) {
                int row = rowA0 + i * 16;
                uint32_t a = as_b +
                    (uint32_t)(row * 32 + (((2 * ks + qselA) ^ localA) << 2)) * 4;
                ldsm4(af[i], a);
            }
#pragma unroll
            for (int jj = 0; jj < 4; ++jj) {
                int row = wn * 64 + (2 * jj + pairB) * 8 + localB;
                uint32_t b = bs_b +
                    (uint32_t)(row * 32 + (((2 * ks + matB) ^ localB) << 2)) * 4;
                uint32_t bf[4];
                ldsm4(bf, b);
                mma_tf32(acc[0][2*jj],   af[0], bf[0], bf[1]);
                mma_tf32(acc[1][2*jj],   af[1], bf[0], bf[1]);
                mma_tf32(acc[0][2*jj+1], af[0], bf[2], bf[3]);
                mma_tf32(acc[1][2*jj+1], af[1], bf[2], bf[3]);
            }
        }
    };

    issue(0, 0); cp_commit();
    issue(1, 1); cp_commit();
    for (int kt = 0; kt < NIT; ++kt) {
        cp_wait<1>();
        __syncthreads();
        compute(kt % 3);
        if (kt + 2 < NIT) issue(kt + 2, (kt + 2) % 3);
        cp_commit();
    }

#pragma unroll
    for (int i = 0; i < 2; ++i) {
        const int r = m0 + wm * 32 + i * 16 + (lane >> 2);
#pragma unroll
        for (int j = 0; j < 8; ++j) {
            const int c = n0 + wn * 64 + j * 8 + ((lane & 3) << 1);
            float2 bi = *(const float2*)&bias[c];
            float v00 = acc[i][j][0] + bi.x, v01 = acc[i][j][1] + bi.y;
            float v10 = acc[i][j][2] + bi.x, v11 = acc[i][j][3] + bi.y;
            if (TF32OUT) {
                uint32_t* Cc = (uint32_t*)Cout;
                *(uint2*)&Cc[(size_t)r * N + c] = make_uint2(f2tf32(v00), f2tf32(v01));
                *(uint2*)&Cc[(size_t)(r + 8) * N + c] = make_uint2(f2tf32(v10), f2tf32(v11));
            } else {
                float* Cc = (float*)Cout;
                *(float2*)&Cc[(size_t)r * N + c]       = make_float2(v00, v01);
                *(float2*)&Cc[(size_t)(r + 8) * N + c] = make_float2(v10, v11);
            }
        }
    }
}

// ===========================================================================
// Tensor-core flash attention (causal) — R8-proven kernel, VERBATIM.
// ===========================================================================
#define KV_STRIDE 132
#define P_STRIDE  68
#define OFF_VB 16896
#define OFF_P  33792
#define ATTN_SMEM ((OFF_P + 128*P_STRIDE) * 4)   // 152,576 B

__global__ __launch_bounds__(256, 1) void attn_tc()
{
    extern __shared__ __align__(16) uint32_t smu[];
    const uint32_t smem_base = smem_u32(smu);
    uint32_t* Ps = smu + OFF_P;     // [128][68]
    uint32_t* Qs = smu;             // staging [128][132] (words 0..16895)

    const int tid  = threadIdx.x;
    const int lane = tid & 31;
    const int warp = tid >> 5;
    const int g = lane >> 2;
    const int t = lane & 3;
    const int qt = 7 - (int)blockIdx.x;
    const int b  = blockIdx.y >> 4, h = blockIdx.y & 15;

    const uint32_t* seq = g_qkvt + (size_t)b * T_ * C3_ + h * D_;
    const uint32_t* Qg = seq + (size_t)(qt * 128) * C3_;
    const uint32_t* Kg = seq + C_;
    const uint32_t* Vg = seq + 2 * C_;

#pragma unroll
    for (int p = 0; p < 16; ++p) {
        int i = tid + (p << 8);
        int r = i >> 5, c4 = (i & 31) << 2;
        *(uint4*)&Qs[r * KV_STRIDE + c4] =
            *(const uint4*)(Qg + (size_t)r * C3_ + c4);
    }
    __syncthreads();

    uint32_t qf[16][4];
    {
        const int m = warp * 16 + g;
#pragma unroll
        for (int ks = 0; ks < 16; ++ks) {
            const int k0 = ks * 8 + t;
            qf[ks][0] = Qs[m * KV_STRIDE + k0];
            qf[ks][1] = Qs[(m + 8) * KV_STRIDE + k0];
            qf[ks][2] = Qs[m * KV_STRIDE + k0 + 4];
            qf[ks][3] = Qs[(m + 8) * KV_STRIDE + k0 + 4];
        }
    }
    __syncthreads();

    float of[16][4];
#pragma unroll
    for (int nf = 0; nf < 16; ++nf)
#pragma unroll
        for (int q = 0; q < 4; ++q) of[nf][q] = 0.f;
    float m0h = -3.0e38f, m1h = -3.0e38f, l0 = 0.f, l1 = 0.f;

    const float scale = 0.08838834764831845f;
    const int rg0 = qt * 128 + warp * 16 + g;
    const int prow = warp * 16 + g;
    const int nt  = 2 * qt + 2;

    auto issueKV = [&](int kt, int s) {
        const int kv0 = kt * 64;
        const uint32_t kb = smem_base + (uint32_t)(s * 8448) * 4;
        const uint32_t vb = smem_base + (uint32_t)(OFF_VB + s * 8448) * 4;
#pragma unroll
        for (int p = 0; p < 8; ++p) {
            int i = tid + (p << 8);
            int r = i >> 5, c4 = (i & 31) << 2;
            cp16(kb + (uint32_t)(r * KV_STRIDE + c4) * 4,
                 Kg + (size_t)(kv0 + r) * C3_ + c4);
            cp16(vb + (uint32_t)(r * KV_STRIDE + c4) * 4,
                 Vg + (size_t)(kv0 + r) * C3_ + c4);
        }
    };

    issueKV(0, 0); cp_commit();

    for (int kt = 0; kt < nt; ++kt) {
        cp_wait<0>();
        __syncthreads();
        if (kt + 1 < nt) { issueKV(kt + 1, (kt + 1) & 1); cp_commit(); }

        const uint32_t* Ks = smu + (kt & 1) * 8448;
        const uint32_t* Vs = smu + OFF_VB + (kt & 1) * 8448;
        const int kv0 = kt * 64;

        float sc[8][4];
#pragma unroll
        for (int j = 0; j < 8; ++j)
#pragma unroll
            for (int q = 0; q < 4; ++q) sc[j][q] = 0.f;

#pragma unroll
        for (int ks = 0; ks < 16; ++ks) {
            const int kd = ks * 8 + t;
#pragma unroll
            for (int j = 0; j < 8; ++j) {
                const uint32_t* kr = &Ks[(j * 8 + g) * KV_STRIDE + kd];
                mma_tf32(sc[j], qf[ks], kr[0], kr[4]);
            }
        }

        {   // half 0
            float mt = -3.0e38f;
#pragma unroll
            for (int j = 0; j < 8; ++j) {
                int cg = kv0 + j * 8 + 2 * t;
                float v0 = sc[j][0] * scale; if (cg > rg0)     v0 = -1.0e9f;
                float v1 = sc[j][1] * scale; if (cg + 1 > rg0) v1 = -1.0e9f;
                sc[j][0] = v0; sc[j][1] = v1;
                mt = fmaxf(mt, fmaxf(v0, v1));
            }
            mt = fmaxf(mt, __shfl_xor_sync(~0u, mt, 1));
            mt = fmaxf(mt, __shfl_xor_sync(~0u, mt, 2));
            float mn = fmaxf(m0h, mt);
            float sum = 0.f;
#pragma unroll
            for (int j = 0; j < 8; ++j) {
                float p0 = __expf(sc[j][0] - mn);
                float p1 = __expf(sc[j][1] - mn);
                sum += p0 + p1;
                sc[j][0] = p0; sc[j][1] = p1;
            }
            sum += __shfl_xor_sync(~0u, sum, 1);
            sum += __shfl_xor_sync(~0u, sum, 2);
            float corr = __expf(m0h - mn);
            l0 = l0 * corr + sum; m0h = mn;
#pragma unroll
            for (int nf = 0; nf < 16; ++nf) { of[nf][0] *= corr; of[nf][1] *= corr; }
        }
        {   // half 1
            float mt = -3.0e38f;
#pragma unroll
            for (int j = 0; j < 8; ++j) {
                int cg = kv0 + j * 8 + 2 * t;
                float v0 = sc[j][2] * scale; if (cg > rg0 + 8)     v0 = -1.0e9f;
                float v1 = sc[j][3] * scale; if (cg + 1 > rg0 + 8) v1 = -1.0e9f;
                sc[j][2] = v0; sc[j][3] = v1;
                mt = fmaxf(mt, fmaxf(v0, v1));
            }
            mt = fmaxf(mt, __shfl_xor_sync(~0u, mt, 1));
            mt = fmaxf(mt, __shfl_xor_sync(~0u, mt, 2));
            float mn = fmaxf(m1h, mt);
            float sum = 0.f;
#pragma unroll
            for (int j = 0; j < 8; ++j) {
                float p0 = __expf(sc[j][2] - mn);
                float p1 = __expf(sc[j][3] - mn);
                sum += p0 + p1;
                sc[j][2] = p0; sc[j][3] = p1;
            }
            sum += __shfl_xor_sync(~0u, sum, 1);
            sum += __shfl_xor_sync(~0u, sum, 2);
            float corr = __expf(m1h - mn);
            l1 = l1 * corr + sum; m1h = mn;
#pragma unroll
            for (int nf = 0; nf < 16; ++nf) { of[nf][2] *= corr; of[nf][3] *= corr; }
        }

#pragma unroll
        for (int j = 0; j < 8; ++j) {
            uint2 u0 = make_uint2(f2tf32(sc[j][0]), f2tf32(sc[j][1]));
            uint2 u1 = make_uint2(f2tf32(sc[j][2]), f2tf32(sc[j][3]));
            *(uint2*)&Ps[prow * P_STRIDE + j * 8 + 2 * t]       = u0;
            *(uint2*)&Ps[(prow + 8) * P_STRIDE + j * 8 + 2 * t] = u1;
        }
        __syncwarp();

        uint32_t pa[8][4];
#pragma unroll
        for (int ks2 = 0; ks2 < 8; ++ks2) {
            const int k0 = ks2 * 8 + t;
            pa[ks2][0] = Ps[prow * P_STRIDE + k0];
            pa[ks2][1] = Ps[(prow + 8) * P_STRIDE + k0];
            pa[ks2][2] = Ps[prow * P_STRIDE + k0 + 4];
            pa[ks2][3] = Ps[(prow + 8) * P_STRIDE + k0 + 4];
        }

#pragma unroll
        for (int ks2 = 0; ks2 < 8; ++ks2) {
            const int kv = ks2 * 8 + t;
#pragma unroll
            for (int nf = 0; nf < 16; ++nf) {
                uint32_t b0 = Vs[kv * KV_STRIDE + nf * 8 + g];
                uint32_t b1 = Vs[(kv + 4) * KV_STRIDE + nf * 8 + g];
                mma_tf32(of[nf], pa[ks2], b0, b1);
            }
        }
    }

    const float inv0 = 1.0f / l0, inv1 = 1.0f / l1;
    const size_t r0 = (size_t)(b*T_ + qt*128 + warp*16 + g) * C_ + h*D_;
#pragma unroll
    for (int nf = 0; nf < 16; ++nf) {
        const int col = nf * 8 + 2 * t;
        *(uint2*)&g_yt[r0 + col] =
            make_uint2(f2tf32(of[nf][0] * inv0), f2tf32(of[nf][1] * inv0));
        *(uint2*)&g_yt[r0 + (size_t)8 * C_ + col] =
            make_uint2(f2tf32(of[nf][2] * inv1), f2tf32(of[nf][3] * inv1));
    }
}

// ---------------------------------------------------------------------------
extern "C" void kernel_launch(void* const* d_in, const int* in_sizes, int n_in,
                              void* d_out, int out_size)
{
    const float* x      = (const float*)d_in[0];
    const float* W_attn = (const float*)d_in[1];
    const float* b_attn = (const float*)d_in[2];
    const float* W_proj = (const float*)d_in[3];
    const float* b_proj = (const float*)d_in[4];
    float* out = (float*)d_out;

    uint32_t *qkvt = nullptr, *xt = nullptr, *wat = nullptr,
             *wpt = nullptr, *yt = nullptr;
    cudaGetSymbolAddress((void**)&qkvt, g_qkvt);
    cudaGetSymbolAddress((void**)&xt,  g_xt);
    cudaGetSymbolAddress((void**)&wat, g_wat);
    cudaGetSymbolAddress((void**)&wpt, g_wpt);
    cudaGetSymbolAddress((void**)&yt,  g_yt);

    cudaFuncSetAttribute(gemm_cp<true>,
                         cudaFuncAttributeMaxDynamicSharedMemorySize, GEMM_SMEM_CP);
    cudaFuncSetAttribute(gemm_cp<false>,
                         cudaFuncAttributeMaxDynamicSharedMemorySize, GEMM_SMEM_CP);
    cudaFuncSetAttribute(attn_tc,
                         cudaFuncAttributeMaxDynamicSharedMemorySize, ATTN_SMEM);

    // 0) one-shot conversions: x (row-major), W matrices TRANSPOSED [N][K]
    int n4 = (B_*T_*C_) / 4;
    cvt_tf32_k<<<(n4 + 255) / 256, 256>>>((const float4*)x, (uint4*)xt, n4);
    transpose_cvt<<<dim3(C3_/32, C_/32), 256>>>(W_attn, wat, C_, C3_);
    transpose_cvt<<<dim3(C_/32,  C_/32), 256>>>(W_proj, wpt, C_, C_);

    // 1) qkv = x @ W_attn + b_attn -> tf32 bits   [8192, 6144]
    gemm_cp<true><<<dim3(C3_/128, (B_*T_)/128), 256, GEMM_SMEM_CP>>>(
        xt, wat, b_attn, qkvt, B_*T_, C3_, C_);

    // 2) causal flash attention -> g_yt (tf32)    [8192, 2048]
    attn_tc<<<dim3(T_/128, B_*H_), 256, ATTN_SMEM>>>();

    // 3) out = y @ W_proj + b_proj                [8192, 2048]
    gemm_cp<false><<<dim3(C_/128, (B_*T_)/128), 256, GEMM_SMEM_CP>>>(
        yt, wpt, b_proj, out, B_*T_, C_, C_);
}

// round 12
// speedup vs baseline: 2.6512x; 1.5857x over previous
#include <cuda_runtime.h>
#include <cuda_fp16.h>
#include <math.h>
#include <stdint.h>

#define B_ 8
#define T_ 1024
#define C_ 2048
#define H_ 16
#define D_ 128
#define C3_ (3*C_)

// Scratch (device globals: allocation-free kernel_launch).
__device__ uint32_t g_qkvt[(size_t)B_*T_*C3_];  // qkv as tf32 bits (attention input)
__device__ __half   g_xh [(size_t)B_*T_*C_];    // x as fp16
__device__ __half   g_wath[(size_t)C_*C3_];     // W_attn^T fp16 [3C][C]
__device__ __half   g_wpth[(size_t)C_*C_];      // W_proj^T fp16 [C][C]
__device__ __half   g_yh [(size_t)B_*T_*C_];    // y as fp16

// ===========================================================================
// helpers (base PTX only — ptxas here targets plain sm_103; no tcgen05)
// ===========================================================================
__device__ __forceinline__ uint32_t f2tf32(float f) {
    uint32_t r;
    asm("cvt.rna.tf32.f32 %0, %1;" : "=r"(r) : "f"(f));
    return r;
}
__device__ __forceinline__ uint32_t smem_u32(const void* p) {
    uint32_t a;
    asm("{ .reg .u64 t; cvta.to.shared.u64 t, %1; cvt.u32.u64 %0, t; }"
        : "=r"(a) : "l"(p));
    return a;
}
__device__ __forceinline__ void mma_tf32(float* d, const uint32_t* a,
                                         uint32_t b0, uint32_t b1) {
    asm volatile(
        "mma.sync.aligned.m16n8k8.row.col.f32.tf32.tf32.f32 "
        "{%0,%1,%2,%3}, {%4,%5,%6,%7}, {%8,%9}, {%0,%1,%2,%3};"
        : "+f"(d[0]), "+f"(d[1]), "+f"(d[2]), "+f"(d[3])
        : "r"(a[0]), "r"(a[1]), "r"(a[2]), "r"(a[3]), "r"(b0), "r"(b1));
}
__device__ __forceinline__ void mma_f16(float* d, const uint32_t* a,
                                        uint32_t b0, uint32_t b1) {
    asm volatile(
        "mma.sync.aligned.m16n8k16.row.col.f32.f16.f16.f32 "
        "{%0,%1,%2,%3}, {%4,%5,%6,%7}, {%8,%9}, {%0,%1,%2,%3};"
        : "+f"(d[0]), "+f"(d[1]), "+f"(d[2]), "+f"(d[3])
        : "r"(a[0]), "r"(a[1]), "r"(a[2]), "r"(a[3]), "r"(b0), "r"(b1));
}
__device__ __forceinline__ void ldsm4(uint32_t* r, uint32_t addr) {
    asm volatile("ldmatrix.sync.aligned.m8n8.x4.shared.b16 {%0,%1,%2,%3}, [%4];"
        : "=r"(r[0]), "=r"(r[1]), "=r"(r[2]), "=r"(r[3]) : "r"(addr));
}
__device__ __forceinline__ void cp16(uint32_t dst, const void* src) {
    asm volatile("cp.async.cg.shared.global [%0], [%1], 16;"
                 :: "r"(dst), "l"(src));
}
__device__ __forceinline__ void cp_commit() {
    asm volatile("cp.async.commit_group;" ::: "memory");
}
template <int N>
__device__ __forceinline__ void cp_wait() {
    asm volatile("cp.async.wait_group %0;" :: "n"(N) : "memory");
}

// ===========================================================================
// elementwise fp32 -> fp16
// ===========================================================================
__global__ void cvt_f16_k(const float4* __restrict__ in,
                          __half2* __restrict__ out, int n4)
{
    int i = blockIdx.x * blockDim.x + threadIdx.x;
    if (i < n4) {
        float4 v = in[i];
        out[2*i]   = __floats2half2_rn(v.x, v.y);
        out[2*i+1] = __floats2half2_rn(v.z, v.w);
    }
}

// ===========================================================================
// transpose + convert: in [Kd][Nd] fp32 -> out [Nd][Kd] fp16
// ===========================================================================
__global__ void transpose_cvt_h(const float* __restrict__ in,
                                __half* __restrict__ out, int Kd, int Nd)
{
    __shared__ float tile[32][33];
    const int k0 = blockIdx.y * 32, n0 = blockIdx.x * 32;
    const int tx = threadIdx.x & 31, ty = threadIdx.x >> 5;
#pragma unroll
    for (int p = 0; p < 4; ++p) {
        int k = ty + p * 8;
        tile[k][tx] = in[(size_t)(k0 + k) * Nd + n0 + tx];
    }
    __syncthreads();
#pragma unroll
    for (int p = 0; p < 4; ++p) {
        int n = ty + p * 8;
        out[(size_t)(n0 + n) * Kd + k0 + tx] = __float2half_rn(tile[tx][n]);
    }
}

// ===========================================================================
// fp16 tensor-core GEMM, 3-stage cp.async pipeline + ldmatrix.
// C[M,N] = A[M,K] @ BT[N,K]^T + bias[N]; A,BT fp16.
// CTA 128x128, BK=64 (128B/row — SAME stage bytes/swizzle as proven kernel).
// 256 thr (8 warps 4x2), warp tile 32x64. Per chunk: 4 k16-steps,
// per step: A 2x ldsm4, B 4x ldsm4, 16 mma.m16n8k16.
// 3 stages x (16KB A + 16KB B) = 96KB; 2 CTAs/SM.
// TF32OUT: store C as tf32 bits (for attention); else fp32.
// ===========================================================================
#define GEMM_SMEM_CP 98304

template <bool TF32OUT>
__global__ __launch_bounds__(256, 2) void gemm_f16(
    const __half* __restrict__ A, const __half* __restrict__ BT,
    const float* __restrict__ bias, void* __restrict__ Cout,
    int M, int N, int K)
{
    extern __shared__ __align__(16) uint32_t sm4[];
    const uint32_t smem_base = smem_u32(sm4);
    const int tid  = threadIdx.x;
    const int lane = tid & 31;
    const int warp = tid >> 5;
    const int wm = warp & 3, wn = warp >> 2;
    const int m0 = blockIdx.y * 128, n0 = blockIdx.x * 128;
    const int NIT = K >> 6;   // BK=64

    float acc[2][8][4];
#pragma unroll
    for (int i = 0; i < 2; ++i)
#pragma unroll
        for (int j = 0; j < 8; ++j)
#pragma unroll
            for (int q = 0; q < 4; ++q) acc[i][j][q] = 0.f;

    auto issue = [&](int kt, int s) {
        const int k0 = kt << 6;
        const uint32_t ab = smem_base + (uint32_t)s * 16384;
#pragma unroll
        for (int p = 0; p < 4; ++p) {
            int i = tid + (p << 8);
            int r = i >> 3, u = i & 7;
            cp16(ab + (uint32_t)(r * 8 + (u ^ (r & 7))) * 16,
                 A + (size_t)(m0 + r) * K + k0 + (u << 3));
        }
        const uint32_t bb = smem_base + 49152u + (uint32_t)s * 16384;
#pragma unroll
        for (int p = 0; p < 4; ++p) {
            int i = tid + (p << 8);
            int r = i >> 3, u = i & 7;
            cp16(bb + (uint32_t)(r * 8 + (u ^ (r & 7))) * 16,
                 BT + (size_t)(n0 + r) * K + k0 + (u << 3));
        }
    };

    // ldmatrix lane geometry
    const int mlocA = lane & 15;          // m within 16-row tile
    const int khA   = lane >> 4;          // k-half (16B unit) for A
    const int nlocB = (lane & 7) + ((lane >> 4) << 3);  // n within 16-row tile
    const int khB   = (lane >> 3) & 1;    // k-half for B

    auto compute = [&](int s) {
        const uint32_t as_b = smem_base + (uint32_t)s * 16384;
        const uint32_t bs_b = smem_base + 49152u + (uint32_t)s * 16384;
#pragma unroll
        for (int ks = 0; ks < 4; ++ks) {
            uint32_t af[2][4];
#pragma unroll
            for (int i = 0; i < 2; ++i) {
                int row = wm * 32 + i * 16 + mlocA;
                int unit = 2 * ks + khA;
                ldsm4(af[i], as_b + (uint32_t)(row * 8 + (unit ^ (row & 7))) * 16);
            }
#pragma unroll
            for (int jj = 0; jj < 4; ++jj) {
                int row = wn * 64 + jj * 16 + nlocB;
                int unit = 2 * ks + khB;
                uint32_t bf[4];
                ldsm4(bf, bs_b + (uint32_t)(row * 8 + (unit ^ (row & 7))) * 16);
                mma_f16(acc[0][2*jj],   af[0], bf[0], bf[1]);
                mma_f16(acc[1][2*jj],   af[1], bf[0], bf[1]);
                mma_f16(acc[0][2*jj+1], af[0], bf[2], bf[3]);
                mma_f16(acc[1][2*jj+1], af[1], bf[2], bf[3]);
            }
        }
    };

    issue(0, 0); cp_commit();
    issue(1, 1); cp_commit();
    for (int kt = 0; kt < NIT; ++kt) {
        cp_wait<1>();
        __syncthreads();
        compute(kt % 3);
        if (kt + 2 < NIT) issue(kt + 2, (kt + 2) % 3);
        cp_commit();
    }

#pragma unroll
    for (int i = 0; i < 2; ++i) {
        const int r = m0 + wm * 32 + i * 16 + (lane >> 2);
#pragma unroll
        for (int j = 0; j < 8; ++j) {
            const int c = n0 + wn * 64 + j * 8 + ((lane & 3) << 1);
            float2 bi = *(const float2*)&bias[c];
            float v00 = acc[i][j][0] + bi.x, v01 = acc[i][j][1] + bi.y;
            float v10 = acc[i][j][2] + bi.x, v11 = acc[i][j][3] + bi.y;
            if (TF32OUT) {
                uint32_t* Cc = (uint32_t*)Cout;
                *(uint2*)&Cc[(size_t)r * N + c] = make_uint2(f2tf32(v00), f2tf32(v01));
                *(uint2*)&Cc[(size_t)(r + 8) * N + c] = make_uint2(f2tf32(v10), f2tf32(v11));
            } else {
                float* Cc = (float*)Cout;
                *(float2*)&Cc[(size_t)r * N + c]       = make_float2(v00, v01);
                *(float2*)&Cc[(size_t)(r + 8) * N + c] = make_float2(v10, v11);
            }
        }
    }
}

// ===========================================================================
// Tensor-core flash attention (causal), tf32 mma — R8-proven kernel.
// ONLY change: epilogue writes y as fp16 (g_yh) for the fp16 proj GEMM.
// ===========================================================================
#define KV_STRIDE 132
#define P_STRIDE  68
#define OFF_VB 16896
#define OFF_P  33792
#define ATTN_SMEM ((OFF_P + 128*P_STRIDE) * 4)   // 152,576 B

__global__ __launch_bounds__(256, 1) void attn_tc()
{
    extern __shared__ __align__(16) uint32_t smu[];
    const uint32_t smem_base = smem_u32(smu);
    uint32_t* Ps = smu + OFF_P;     // [128][68]
    uint32_t* Qs = smu;             // staging [128][132]

    const int tid  = threadIdx.x;
    const int lane = tid & 31;
    const int warp = tid >> 5;
    const int g = lane >> 2;
    const int t = lane & 3;
    const int qt = 7 - (int)blockIdx.x;
    const int b  = blockIdx.y >> 4, h = blockIdx.y & 15;

    const uint32_t* seq = g_qkvt + (size_t)b * T_ * C3_ + h * D_;
    const uint32_t* Qg = seq + (size_t)(qt * 128) * C3_;
    const uint32_t* Kg = seq + C_;
    const uint32_t* Vg = seq + 2 * C_;

#pragma unroll
    for (int p = 0; p < 16; ++p) {
        int i = tid + (p << 8);
        int r = i >> 5, c4 = (i & 31) << 2;
        *(uint4*)&Qs[r * KV_STRIDE + c4] =
            *(const uint4*)(Qg + (size_t)r * C3_ + c4);
    }
    __syncthreads();

    uint32_t qf[16][4];
    {
        const int m = warp * 16 + g;
#pragma unroll
        for (int ks = 0; ks < 16; ++ks) {
            const int k0 = ks * 8 + t;
            qf[ks][0] = Qs[m * KV_STRIDE + k0];
            qf[ks][1] = Qs[(m + 8) * KV_STRIDE + k0];
            qf[ks][2] = Qs[m * KV_STRIDE + k0 + 4];
            qf[ks][3] = Qs[(m + 8) * KV_STRIDE + k0 + 4];
        }
    }
    __syncthreads();

    float of[16][4];
#pragma unroll
    for (int nf = 0; nf < 16; ++nf)
#pragma unroll
        for (int q = 0; q < 4; ++q) of[nf][q] = 0.f;
    float m0h = -3.0e38f, m1h = -3.0e38f, l0 = 0.f, l1 = 0.f;

    const float scale = 0.08838834764831845f;
    const int rg0 = qt * 128 + warp * 16 + g;
    const int prow = warp * 16 + g;
    const int nt  = 2 * qt + 2;

    auto issueKV = [&](int kt, int s) {
        const int kv0 = kt * 64;
        const uint32_t kb = smem_base + (uint32_t)(s * 8448) * 4;
        const uint32_t vb = smem_base + (uint32_t)(OFF_VB + s * 8448) * 4;
#pragma unroll
        for (int p = 0; p < 8; ++p) {
            int i = tid + (p << 8);
            int r = i >> 5, c4 = (i & 31) << 2;
            cp16(kb + (uint32_t)(r * KV_STRIDE + c4) * 4,
                 Kg + (size_t)(kv0 + r) * C3_ + c4);
            cp16(vb + (uint32_t)(r * KV_STRIDE + c4) * 4,
                 Vg + (size_t)(kv0 + r) * C3_ + c4);
        }
    };

    issueKV(0, 0); cp_commit();

    for (int kt = 0; kt < nt; ++kt) {
        cp_wait<0>();
        __syncthreads();
        if (kt + 1 < nt) { issueKV(kt + 1, (kt + 1) & 1); cp_commit(); }

        const uint32_t* Ks = smu + (kt & 1) * 8448;
        const uint32_t* Vs = smu + OFF_VB + (kt & 1) * 8448;
        const int kv0 = kt * 64;

        float sc[8][4];
#pragma unroll
        for (int j = 0; j < 8; ++j)
#pragma unroll
            for (int q = 0; q < 4; ++q) sc[j][q] = 0.f;

#pragma unroll
        for (int ks = 0; ks < 16; ++ks) {
            const int kd = ks * 8 + t;
#pragma unroll
            for (int j = 0; j < 8; ++j) {
                const uint32_t* kr = &Ks[(j * 8 + g) * KV_STRIDE + kd];
                mma_tf32(sc[j], qf[ks], kr[0], kr[4]);
            }
        }

        {   // half 0
            float mt = -3.0e38f;
#pragma unroll
            for (int j = 0; j < 8; ++j) {
                int cg = kv0 + j * 8 + 2 * t;
                float v0 = sc[j][0] * scale; if (cg > rg0)     v0 = -1.0e9f;
                float v1 = sc[j][1] * scale; if (cg + 1 > rg0) v1 = -1.0e9f;
                sc[j][0] = v0; sc[j][1] = v1;
                mt = fmaxf(mt, fmaxf(v0, v1));
            }
            mt = fmaxf(mt, __shfl_xor_sync(~0u, mt, 1));
            mt = fmaxf(mt, __shfl_xor_sync(~0u, mt, 2));
            float mn = fmaxf(m0h, mt);
            float sum = 0.f;
#pragma unroll
            for (int j = 0; j < 8; ++j) {
                float p0 = __expf(sc[j][0] - mn);
                float p1 = __expf(sc[j][1] - mn);
                sum += p0 + p1;
                sc[j][0] = p0; sc[j][1] = p1;
            }
            sum += __shfl_xor_sync(~0u, sum, 1);
            sum += __shfl_xor_sync(~0u, sum, 2);
            float corr = __expf(m0h - mn);
            l0 = l0 * corr + sum; m0h = mn;
#pragma unroll
            for (int nf = 0; nf < 16; ++nf) { of[nf][0] *= corr; of[nf][1] *= corr; }
        }
        {   // half 1
            float mt = -3.0e38f;
#pragma unroll
            for (int j = 0; j < 8; ++j) {
                int cg = kv0 + j * 8 + 2 * t;
                float v0 = sc[j][2] * scale; if (cg > rg0 + 8)     v0 = -1.0e9f;
                float v1 = sc[j][3] * scale; if (cg + 1 > rg0 + 8) v1 = -1.0e9f;
                sc[j][2] = v0; sc[j][3] = v1;
                mt = fmaxf(mt, fmaxf(v0, v1));
            }
            mt = fmaxf(mt, __shfl_xor_sync(~0u, mt, 1));
            mt = fmaxf(mt, __shfl_xor_sync(~0u, mt, 2));
            float mn = fmaxf(m1h, mt);
            float sum = 0.f;
#pragma unroll
            for (int j = 0; j < 8; ++j) {
                float p0 = __expf(sc[j][2] - mn);
                float p1 = __expf(sc[j][3] - mn);
                sum += p0 + p1;
                sc[j][2] = p0; sc[j][3] = p1;
            }
            sum += __shfl_xor_sync(~0u, sum, 1);
            sum += __shfl_xor_sync(~0u, sum, 2);
            float corr = __expf(m1h - mn);
            l1 = l1 * corr + sum; m1h = mn;
#pragma unroll
            for (int nf = 0; nf < 16; ++nf) { of[nf][2] *= corr; of[nf][3] *= corr; }
        }

#pragma unroll
        for (int j = 0; j < 8; ++j) {
            uint2 u0 = make_uint2(f2tf32(sc[j][0]), f2tf32(sc[j][1]));
            uint2 u1 = make_uint2(f2tf32(sc[j][2]), f2tf32(sc[j][3]));
            *(uint2*)&Ps[prow * P_STRIDE + j * 8 + 2 * t]       = u0;
            *(uint2*)&Ps[(prow + 8) * P_STRIDE + j * 8 + 2 * t] = u1;
        }
        __syncwarp();

        uint32_t pa[8][4];
#pragma unroll
        for (int ks2 = 0; ks2 < 8; ++ks2) {
            const int k0 = ks2 * 8 + t;
            pa[ks2][0] = Ps[prow * P_STRIDE + k0];
            pa[ks2][1] = Ps[(prow + 8) * P_STRIDE + k0];
            pa[ks2][2] = Ps[prow * P_STRIDE + k0 + 4];
            pa[ks2][3] = Ps[(prow + 8) * P_STRIDE + k0 + 4];
        }

#pragma unroll
        for (int ks2 = 0; ks2 < 8; ++ks2) {
            const int kv = ks2 * 8 + t;
#pragma unroll
            for (int nf = 0; nf < 16; ++nf) {
                uint32_t b0 = Vs[kv * KV_STRIDE + nf * 8 + g];
                uint32_t b1 = Vs[(kv + 4) * KV_STRIDE + nf * 8 + g];
                mma_tf32(of[nf], pa[ks2], b0, b1);
            }
        }
    }

    // ---- epilogue: O/l -> g_yh (fp16) with head merge ----
    const float inv0 = 1.0f / l0, inv1 = 1.0f / l1;
    const size_t r0 = (size_t)(b*T_ + qt*128 + warp*16 + g) * C_ + h*D_;
#pragma unroll
    for (int nf = 0; nf < 16; ++nf) {
        const int col = nf * 8 + 2 * t;
        *(__half2*)&g_yh[r0 + col] =
            __floats2half2_rn(of[nf][0] * inv0, of[nf][1] * inv0);
        *(__half2*)&g_yh[r0 + (size_t)8 * C_ + col] =
            __floats2half2_rn(of[nf][2] * inv1, of[nf][3] * inv1);
    }
}

// ---------------------------------------------------------------------------
extern "C" void kernel_launch(void* const* d_in, const int* in_sizes, int n_in,
                              void* d_out, int out_size)
{
    const float* x      = (const float*)d_in[0];
    const float* W_attn = (const float*)d_in[1];
    const float* b_attn = (const float*)d_in[2];
    const float* W_proj = (const float*)d_in[3];
    const float* b_proj = (const float*)d_in[4];
    float* out = (float*)d_out;

    uint32_t* qkvt = nullptr;
    __half *xh = nullptr, *wath = nullptr, *wpth = nullptr, *yh = nullptr;
    cudaGetSymbolAddress((void**)&qkvt, g_qkvt);
    cudaGetSymbolAddress((void**)&xh,   g_xh);
    cudaGetSymbolAddress((void**)&wath, g_wath);
    cudaGetSymbolAddress((void**)&wpth, g_wpth);
    cudaGetSymbolAddress((void**)&yh,   g_yh);

    cudaFuncSetAttribute(gemm_f16<true>,
                         cudaFuncAttributeMaxDynamicSharedMemorySize, GEMM_SMEM_CP);
    cudaFuncSetAttribute(gemm_f16<false>,
                         cudaFuncAttributeMaxDynamicSharedMemorySize, GEMM_SMEM_CP);
    cudaFuncSetAttribute(attn_tc,
                         cudaFuncAttributeMaxDynamicSharedMemorySize, ATTN_SMEM);

    // 0) one-shot conversions: x -> fp16 row-major, W -> fp16 TRANSPOSED [N][K]
    int n4 = (B_*T_*C_) / 4;
    cvt_f16_k<<<(n4 + 255) / 256, 256>>>((const float4*)x, (__half2*)xh, n4);
    transpose_cvt_h<<<dim3(C3_/32, C_/32), 256>>>(W_attn, wath, C_, C3_);
    transpose_cvt_h<<<dim3(C_/32,  C_/32), 256>>>(W_proj, wpth, C_, C_);

    // 1) qkv = x @ W_attn + b_attn -> tf32 bits   [8192, 6144]
    gemm_f16<true><<<dim3(C3_/128, (B_*T_)/128), 256, GEMM_SMEM_CP>>>(
        xh, wath, b_attn, qkvt, B_*T_, C3_, C_);

    // 2) causal flash attention -> g_yh (fp16)    [8192, 2048]
    attn_tc<<<dim3(T_/128, B_*H_), 256, ATTN_SMEM>>>();

    // 3) out = y @ W_proj + b_proj                [8192, 2048]
    gemm_f16<false><<<dim3(C_/128, (B_*T_)/128), 256, GEMM_SMEM_CP>>>(
        yh, wpth, b_proj, out, B_*T_, C_, C_);
}

// round 13
// speedup vs baseline: 3.3168x; 1.2511x over previous
#include <cuda_runtime.h>
#include <cuda_fp16.h>
#include <math.h>
#include <stdint.h>

#define B_ 8
#define T_ 1024
#define C_ 2048
#define H_ 16
#define D_ 128
#define C3_ (3*C_)

// Scratch (device globals: allocation-free kernel_launch).
__device__ __half g_qkvh[(size_t)B_*T_*C3_];   // qkv as fp16 (attention input)
__device__ __half g_xh  [(size_t)B_*T_*C_];    // x as fp16
__device__ __half g_wath[(size_t)C_*C3_];      // W_attn^T fp16 [3C][C]
__device__ __half g_wpth[(size_t)C_*C_];       // W_proj^T fp16 [C][C]
__device__ __half g_yh  [(size_t)B_*T_*C_];    // y as fp16

// ===========================================================================
// helpers (base PTX only — ptxas here targets plain sm_103; no tcgen05)
// ===========================================================================
__device__ __forceinline__ uint32_t smem_u32(const void* p) {
    uint32_t a;
    asm("{ .reg .u64 t; cvta.to.shared.u64 t, %1; cvt.u32.u64 %0, t; }"
        : "=r"(a) : "l"(p));
    return a;
}
__device__ __forceinline__ void mma_f16(float* d, const uint32_t* a,
                                        uint32_t b0, uint32_t b1) {
    asm volatile(
        "mma.sync.aligned.m16n8k16.row.col.f32.f16.f16.f32 "
        "{%0,%1,%2,%3}, {%4,%5,%6,%7}, {%8,%9}, {%0,%1,%2,%3};"
        : "+f"(d[0]), "+f"(d[1]), "+f"(d[2]), "+f"(d[3])
        : "r"(a[0]), "r"(a[1]), "r"(a[2]), "r"(a[3]), "r"(b0), "r"(b1));
}
__device__ __forceinline__ void ldsm4(uint32_t* r, uint32_t addr) {
    asm volatile("ldmatrix.sync.aligned.m8n8.x4.shared.b16 {%0,%1,%2,%3}, [%4];"
        : "=r"(r[0]), "=r"(r[1]), "=r"(r[2]), "=r"(r[3]) : "r"(addr));
}
__device__ __forceinline__ void ldsm4t(uint32_t* r, uint32_t addr) {
    asm volatile("ldmatrix.sync.aligned.m8n8.x4.trans.shared.b16 {%0,%1,%2,%3}, [%4];"
        : "=r"(r[0]), "=r"(r[1]), "=r"(r[2]), "=r"(r[3]) : "r"(addr));
}
__device__ __forceinline__ void cp16(uint32_t dst, const void* src) {
    asm volatile("cp.async.cg.shared.global [%0], [%1], 16;"
                 :: "r"(dst), "l"(src));
}
__device__ __forceinline__ void cp_commit() {
    asm volatile("cp.async.commit_group;" ::: "memory");
}
template <int N>
__device__ __forceinline__ void cp_wait() {
    asm volatile("cp.async.wait_group %0;" :: "n"(N) : "memory");
}
__device__ __forceinline__ uint32_t fh2(float a, float b) {
    __half2 h = __floats2half2_rn(a, b);
    return *(uint32_t*)&h;
}

// ===========================================================================
// elementwise fp32 -> fp16
// ===========================================================================
__global__ void cvt_f16_k(const float4* __restrict__ in,
                          __half2* __restrict__ out, int n4)
{
    int i = blockIdx.x * blockDim.x + threadIdx.x;
    if (i < n4) {
        float4 v = in[i];
        out[2*i]   = __floats2half2_rn(v.x, v.y);
        out[2*i+1] = __floats2half2_rn(v.z, v.w);
    }
}

// ===========================================================================
// transpose + convert: in [Kd][Nd] fp32 -> out [Nd][Kd] fp16
// ===========================================================================
__global__ void transpose_cvt_h(const float* __restrict__ in,
                                __half* __restrict__ out, int Kd, int Nd)
{
    __shared__ float tile[32][33];
    const int k0 = blockIdx.y * 32, n0 = blockIdx.x * 32;
    const int tx = threadIdx.x & 31, ty = threadIdx.x >> 5;
#pragma unroll
    for (int p = 0; p < 4; ++p) {
        int k = ty + p * 8;
        tile[k][tx] = in[(size_t)(k0 + k) * Nd + n0 + tx];
    }
    __syncthreads();
#pragma unroll
    for (int p = 0; p < 4; ++p) {
        int n = ty + p * 8;
        out[(size_t)(n0 + n) * Kd + k0 + tx] = __float2half_rn(tile[tx][n]);
    }
}

// ===========================================================================
// fp16 tensor-core GEMM, 3-stage cp.async pipeline + ldmatrix (R11-proven).
// F16OUT: store C as fp16 (for attention); else fp32.
// ===========================================================================
#define GEMM_SMEM_CP 98304

template <bool F16OUT>
__global__ __launch_bounds__(256, 2) void gemm_f16(
    const __half* __restrict__ A, const __half* __restrict__ BT,
    const float* __restrict__ bias, void* __restrict__ Cout,
    int M, int N, int K)
{
    extern __shared__ __align__(16) uint32_t sm4[];
    const uint32_t smem_base = smem_u32(sm4);
    const int tid  = threadIdx.x;
    const int lane = tid & 31;
    const int warp = tid >> 5;
    const int wm = warp & 3, wn = warp >> 2;
    const int m0 = blockIdx.y * 128, n0 = blockIdx.x * 128;
    const int NIT = K >> 6;   // BK=64

    float acc[2][8][4];
#pragma unroll
    for (int i = 0; i < 2; ++i)
#pragma unroll
        for (int j = 0; j < 8; ++j)
#pragma unroll
            for (int q = 0; q < 4; ++q) acc[i][j][q] = 0.f;

    auto issue = [&](int kt, int s) {
        const int k0 = kt << 6;
        const uint32_t ab = smem_base + (uint32_t)s * 16384;
#pragma unroll
        for (int p = 0; p < 4; ++p) {
            int i = tid + (p << 8);
            int r = i >> 3, u = i & 7;
            cp16(ab + (uint32_t)(r * 8 + (u ^ (r & 7))) * 16,
                 A + (size_t)(m0 + r) * K + k0 + (u << 3));
        }
        const uint32_t bb = smem_base + 49152u + (uint32_t)s * 16384;
#pragma unroll
        for (int p = 0; p < 4; ++p) {
            int i = tid + (p << 8);
            int r = i >> 3, u = i & 7;
            cp16(bb + (uint32_t)(r * 8 + (u ^ (r & 7))) * 16,
                 BT + (size_t)(n0 + r) * K + k0 + (u << 3));
        }
    };

    const int mlocA = lane & 15;
    const int khA   = lane >> 4;
    const int nlocB = (lane & 7) + ((lane >> 4) << 3);
    const int khB   = (lane >> 3) & 1;

    auto compute = [&](int s) {
        const uint32_t as_b = smem_base + (uint32_t)s * 16384;
        const uint32_t bs_b = smem_base + 49152u + (uint32_t)s * 16384;
#pragma unroll
        for (int ks = 0; ks < 4; ++ks) {
            uint32_t af[2][4];
#pragma unroll
            for (int i = 0; i < 2; ++i) {
                int row = wm * 32 + i * 16 + mlocA;
                int unit = 2 * ks + khA;
                ldsm4(af[i], as_b + (uint32_t)(row * 8 + (unit ^ (row & 7))) * 16);
            }
#pragma unroll
            for (int jj = 0; jj < 4; ++jj) {
                int row = wn * 64 + jj * 16 + nlocB;
                int unit = 2 * ks + khB;
                uint32_t bf[4];
                ldsm4(bf, bs_b + (uint32_t)(row * 8 + (unit ^ (row & 7))) * 16);
                mma_f16(acc[0][2*jj],   af[0], bf[0], bf[1]);
                mma_f16(acc[1][2*jj],   af[1], bf[0], bf[1]);
                mma_f16(acc[0][2*jj+1], af[0], bf[2], bf[3]);
                mma_f16(acc[1][2*jj+1], af[1], bf[2], bf[3]);
            }
        }
    };

    issue(0, 0); cp_commit();
    issue(1, 1); cp_commit();
    for (int kt = 0; kt < NIT; ++kt) {
        cp_wait<1>();
        __syncthreads();
        compute(kt % 3);
        if (kt + 2 < NIT) issue(kt + 2, (kt + 2) % 3);
        cp_commit();
    }

#pragma unroll
    for (int i = 0; i < 2; ++i) {
        const int r = m0 + wm * 32 + i * 16 + (lane >> 2);
#pragma unroll
        for (int j = 0; j < 8; ++j) {
            const int c = n0 + wn * 64 + j * 8 + ((lane & 3) << 1);
            float2 bi = *(const float2*)&bias[c];
            float v00 = acc[i][j][0] + bi.x, v01 = acc[i][j][1] + bi.y;
            float v10 = acc[i][j][2] + bi.x, v11 = acc[i][j][3] + bi.y;
            if (F16OUT) {
                __half* Ch = (__half*)Cout;
                *(__half2*)&Ch[(size_t)r * N + c]       = __floats2half2_rn(v00, v01);
                *(__half2*)&Ch[(size_t)(r + 8) * N + c] = __floats2half2_rn(v10, v11);
            } else {
                float* Cc = (float*)Cout;
                *(float2*)&Cc[(size_t)r * N + c]       = make_float2(v00, v01);
                *(float2*)&Cc[(size_t)(r + 8) * N + c] = make_float2(v10, v11);
            }
        }
    }
}

// ===========================================================================
// fp16 tensor-core flash attention (causal), fp32 softmax/accum.
// Grid (8, B*H), 256 thr = 8 warps. Q-tile 128, KV-tile 64, mma.m16n8k16.
// K,V tiles row-major [64 kv][136 d] halves (stride 68 words: every ldmatrix
// phase and scalar frag read is bank-conflict-free). K via ldmatrix.x4,
// V via ldmatrix.x4.trans (k-major access from row-major storage).
// P: f16 C-frag -> A-frag DIRECT register pack (no smem round trip).
// Double-buffered cp.async K/V (R8-proven schedule).
// ===========================================================================
#define ATTN_SMEM 69632   // 2 x (K 17408B + V 17408B); Q staging reuses K region

__global__ __launch_bounds__(256, 1) void attn_tc()
{
    extern __shared__ __align__(16) uint32_t smu[];
    const uint32_t smem_base = smem_u32(smu);

    const int tid  = threadIdx.x;
    const int lane = tid & 31;
    const int warp = tid >> 5;
    const int g = lane >> 2;
    const int t = lane & 3;
    const int qt = 7 - (int)blockIdx.x;
    const int b  = blockIdx.y >> 4, h = blockIdx.y & 15;

    const __half* seq = g_qkvh + (size_t)b * T_ * C3_ + h * D_;
    const __half* Qg = seq + (size_t)(qt * 128) * C3_;
    const __half* Kg = seq + C_;
    const __half* Vg = seq + 2 * C_;

    // ---- stage Q [128][136] halves (words r*68 + u*4), lift A-frags ----
#pragma unroll
    for (int p = 0; p < 8; ++p) {
        int i = tid + (p << 8);
        int r = i >> 4, u = i & 15;
        *(uint4*)&smu[r * 68 + u * 4] =
            *(const uint4*)(Qg + (size_t)r * C3_ + u * 8);
    }
    __syncthreads();

    uint32_t qf[8][4];
    {
        const int m = warp * 16 + g;
#pragma unroll
        for (int ks = 0; ks < 8; ++ks) {
            qf[ks][0] = smu[m * 68 + 8 * ks + t];
            qf[ks][1] = smu[(m + 8) * 68 + 8 * ks + t];
            qf[ks][2] = smu[m * 68 + 8 * ks + t + 4];
            qf[ks][3] = smu[(m + 8) * 68 + 8 * ks + t + 4];
        }
    }
    __syncthreads();   // frags lifted before issue(0) overwrites staging

    float of[16][4];
#pragma unroll
    for (int nf = 0; nf < 16; ++nf)
#pragma unroll
        for (int q = 0; q < 4; ++q) of[nf][q] = 0.f;
    float m0h = -3.0e38f, m1h = -3.0e38f, l0 = 0.f, l1 = 0.f;

    const float scale = 0.08838834764831845f;   // 1/sqrt(128)
    const int rg0 = qt * 128 + warp * 16 + g;
    const int nt  = 2 * qt + 2;

    // ldmatrix lane geometry
    const int rowB = (lane & 7) + ((lane >> 4) << 3);   // K x4: +16*jj
    const int colB = ((lane >> 3) & 1) * 8;             // + 16*ks (halves)
    const int rowV = (lane & 7) + (((lane >> 3) & 1) << 3);  // + 16*ks2
    const int colV = (lane >> 4) * 8;                   // + 16*nn (halves)

    auto issueKV = [&](int kt, int s) {
        const int kv0 = kt * 64;
        const uint32_t kb = smem_base + (uint32_t)s * 17408;
        const uint32_t vb = smem_base + 34816u + (uint32_t)s * 17408;
#pragma unroll
        for (int p = 0; p < 4; ++p) {
            int i = tid + (p << 8);
            int r = i >> 4, u = i & 15;
            cp16(kb + (uint32_t)(r * 272 + u * 16),
                 Kg + (size_t)(kv0 + r) * C3_ + u * 8);
            cp16(vb + (uint32_t)(r * 272 + u * 16),
                 Vg + (size_t)(kv0 + r) * C3_ + u * 8);
        }
    };

    issueKV(0, 0); cp_commit();

    for (int kt = 0; kt < nt; ++kt) {
        cp_wait<0>();
        __syncthreads();
        if (kt + 1 < nt) { issueKV(kt + 1, (kt + 1) & 1); cp_commit(); }

        const uint32_t kbase = smem_base + (uint32_t)(kt & 1) * 17408;
        const uint32_t vbase = smem_base + 34816u + (uint32_t)(kt & 1) * 17408;
        const int kv0 = kt * 64;

        // ---- S = Q K^T : warp 16 x 64, mma.m16n8k16 ----
        float sc[8][4];
#pragma unroll
        for (int j = 0; j < 8; ++j)
#pragma unroll
            for (int q = 0; q < 4; ++q) sc[j][q] = 0.f;

#pragma unroll
        for (int ks = 0; ks < 8; ++ks) {
#pragma unroll
            for (int jj = 0; jj < 4; ++jj) {
                uint32_t bf[4];
                int row = jj * 16 + rowB;
                int colh = ks * 16 + colB;
                ldsm4(bf, kbase + (uint32_t)(row * 136 + colh) * 2);
                mma_f16(sc[2*jj],   qf[ks], bf[0], bf[1]);
                mma_f16(sc[2*jj+1], qf[ks], bf[2], bf[3]);
            }
        }

        // ---- online softmax (C-frag registers) ----
        {   // half 0: rows rg0
            float mt = -3.0e38f;
#pragma unroll
            for (int j = 0; j < 8; ++j) {
                int cg = kv0 + j * 8 + 2 * t;
                float v0 = sc[j][0] * scale; if (cg > rg0)     v0 = -1.0e9f;
                float v1 = sc[j][1] * scale; if (cg + 1 > rg0) v1 = -1.0e9f;
                sc[j][0] = v0; sc[j][1] = v1;
                mt = fmaxf(mt, fmaxf(v0, v1));
            }
            mt = fmaxf(mt, __shfl_xor_sync(~0u, mt, 1));
            mt = fmaxf(mt, __shfl_xor_sync(~0u, mt, 2));
            float mn = fmaxf(m0h, mt);
            float sum = 0.f;
#pragma unroll
            for (int j = 0; j < 8; ++j) {
                float p0 = __expf(sc[j][0] - mn);
                float p1 = __expf(sc[j][1] - mn);
                sum += p0 + p1;
                sc[j][0] = p0; sc[j][1] = p1;
            }
            sum += __shfl_xor_sync(~0u, sum, 1);
            sum += __shfl_xor_sync(~0u, sum, 2);
            float corr = __expf(m0h - mn);
            l0 = l0 * corr + sum; m0h = mn;
#pragma unroll
            for (int nf = 0; nf < 16; ++nf) { of[nf][0] *= corr; of[nf][1] *= corr; }
        }
        {   // half 1: rows rg0+8
            float mt = -3.0e38f;
#pragma unroll
            for (int j = 0; j < 8; ++j) {
                int cg = kv0 + j * 8 + 2 * t;
                float v0 = sc[j][2] * scale; if (cg > rg0 + 8)     v0 = -1.0e9f;
                float v1 = sc[j][3] * scale; if (cg + 1 > rg0 + 8) v1 = -1.0e9f;
                sc[j][2] = v0; sc[j][3] = v1;
                mt = fmaxf(mt, fmaxf(v0, v1));
            }
            mt = fmaxf(mt, __shfl_xor_sync(~0u, mt, 1));
            mt = fmaxf(mt, __shfl_xor_sync(~0u, mt, 2));
            float mn = fmaxf(m1h, mt);
            float sum = 0.f;
#pragma unroll
            for (int j = 0; j < 8; ++j) {
                float p0 = __expf(sc[j][2] - mn);
                float p1 = __expf(sc[j][3] - mn);
                sum += p0 + p1;
                sc[j][2] = p0; sc[j][3] = p1;
            }
            sum += __shfl_xor_sync(~0u, sum, 1);
            sum += __shfl_xor_sync(~0u, sum, 2);
            float corr = __expf(m1h - mn);
            l1 = l1 * corr + sum; m1h = mn;
#pragma unroll
            for (int nf = 0; nf < 16; ++nf) { of[nf][2] *= corr; of[nf][3] *= corr; }
        }

        // ---- P: C-frag -> A-frag DIRECT pack (f16 layouts align, j=2ks2{,+1}) ----
        uint32_t pa[4][4];
#pragma unroll
        for (int ks2 = 0; ks2 < 4; ++ks2) {
            pa[ks2][0] = fh2(sc[2*ks2][0],   sc[2*ks2][1]);
            pa[ks2][1] = fh2(sc[2*ks2][2],   sc[2*ks2][3]);
            pa[ks2][2] = fh2(sc[2*ks2+1][0], sc[2*ks2+1][1]);
            pa[ks2][3] = fh2(sc[2*ks2+1][2], sc[2*ks2+1][3]);
        }

        // ---- O += P V : warp 16 x 128, V via ldmatrix.trans ----
#pragma unroll
        for (int ks2 = 0; ks2 < 4; ++ks2) {
#pragma unroll
            for (int nn = 0; nn < 8; ++nn) {
                uint32_t bf[4];
                int row = ks2 * 16 + rowV;
                int cold = nn * 16 + colV;
                ldsm4t(bf, vbase + (uint32_t)(row * 136 + cold) * 2);
                mma_f16(of[2*nn],   pa[ks2], bf[0], bf[1]);
                mma_f16(of[2*nn+1], pa[ks2], bf[2], bf[3]);
            }
        }
    }

    // ---- epilogue: O/l -> g_yh (fp16) with head merge ----
    const float inv0 = 1.0f / l0, inv1 = 1.0f / l1;
    const size_t r0 = (size_t)(b*T_ + qt*128 + warp*16 + g) * C_ + h*D_;
#pragma unroll
    for (int nf = 0; nf < 16; ++nf) {
        const int col = nf * 8 + 2 * t;
        *(__half2*)&g_yh[r0 + col] =
            __floats2half2_rn(of[nf][0] * inv0, of[nf][1] * inv0);
        *(__half2*)&g_yh[r0 + (size_t)8 * C_ + col] =
            __floats2half2_rn(of[nf][2] * inv1, of[nf][3] * inv1);
    }
}

// ---------------------------------------------------------------------------
extern "C" void kernel_launch(void* const* d_in, const int* in_sizes, int n_in,
                              void* d_out, int out_size)
{
    const float* x      = (const float*)d_in[0];
    const float* W_attn = (const float*)d_in[1];
    const float* b_attn = (const float*)d_in[2];
    const float* W_proj = (const float*)d_in[3];
    const float* b_proj = (const float*)d_in[4];
    float* out = (float*)d_out;

    __half *qkvh = nullptr, *xh = nullptr, *wath = nullptr,
           *wpth = nullptr, *yh = nullptr;
    cudaGetSymbolAddress((void**)&qkvh, g_qkvh);
    cudaGetSymbolAddress((void**)&xh,   g_xh);
    cudaGetSymbolAddress((void**)&wath, g_wath);
    cudaGetSymbolAddress((void**)&wpth, g_wpth);
    cudaGetSymbolAddress((void**)&yh,   g_yh);

    cudaFuncSetAttribute(gemm_f16<true>,
                         cudaFuncAttributeMaxDynamicSharedMemorySize, GEMM_SMEM_CP);
    cudaFuncSetAttribute(gemm_f16<false>,
                         cudaFuncAttributeMaxDynamicSharedMemorySize, GEMM_SMEM_CP);
    cudaFuncSetAttribute(attn_tc,
                         cudaFuncAttributeMaxDynamicSharedMemorySize, ATTN_SMEM);

    // 0) one-shot conversions: x -> fp16 row-major, W -> fp16 TRANSPOSED [N][K]
    int n4 = (B_*T_*C_) / 4;
    cvt_f16_k<<<(n4 + 255) / 256, 256>>>((const float4*)x, (__half2*)xh, n4);
    transpose_cvt_h<<<dim3(C3_/32, C_/32), 256>>>(W_attn, wath, C_, C3_);
    transpose_cvt_h<<<dim3(C_/32,  C_/32), 256>>>(W_proj, wpth, C_, C_);

    // 1) qkv = x @ W_attn + b_attn -> fp16        [8192, 6144]
    gemm_f16<true><<<dim3(C3_/128, (B_*T_)/128), 256, GEMM_SMEM_CP>>>(
        xh, wath, b_attn, qkvh, B_*T_, C3_, C_);

    // 2) causal flash attention -> g_yh (fp16)    [8192, 2048]
    attn_tc<<<dim3(T_/128, B_*H_), 256, ATTN_SMEM>>>();

    // 3) out = y @ W_proj + b_proj                [8192, 2048]
    gemm_f16<false><<<dim3(C_/128, (B_*T_)/128), 256, GEMM_SMEM_CP>>>(
        yh, wpth, b_proj, out, B_*T_, C_, C_);
}

// round 15
// speedup vs baseline: 3.3705x; 1.0162x over previous
#include <cuda_runtime.h>
#include <cuda_fp16.h>
#include <math.h>
#include <stdint.h>

#define B_ 8
#define T_ 1024
#define C_ 2048
#define H_ 16
#define D_ 128
#define C3_ (3*C_)

// Scratch (device globals: allocation-free kernel_launch).
__device__ __half g_qkvh[(size_t)B_*T_*C3_];   // qkv as fp16 (attention input)
__device__ __half g_xh  [(size_t)B_*T_*C_];    // x as fp16
__device__ __half g_wath[(size_t)C_*C3_];      // W_attn^T fp16 [3C][C]
__device__ __half g_wpth[(size_t)C_*C_];       // W_proj^T fp16 [C][C]
__device__ __half g_yh  [(size_t)B_*T_*C_];    // y as fp16

// ===========================================================================
// helpers (base PTX only — ptxas here targets plain sm_103; no tcgen05)
// ===========================================================================
__device__ __forceinline__ uint32_t smem_u32(const void* p) {
    uint32_t a;
    asm("{ .reg .u64 t; cvta.to.shared.u64 t, %1; cvt.u32.u64 %0, t; }"
        : "=r"(a) : "l"(p));
    return a;
}
__device__ __forceinline__ void mma_f16(float* d, const uint32_t* a,
                                        uint32_t b0, uint32_t b1) {
    asm volatile(
        "mma.sync.aligned.m16n8k16.row.col.f32.f16.f16.f32 "
        "{%0,%1,%2,%3}, {%4,%5,%6,%7}, {%8,%9}, {%0,%1,%2,%3};"
        : "+f"(d[0]), "+f"(d[1]), "+f"(d[2]), "+f"(d[3])
        : "r"(a[0]), "r"(a[1]), "r"(a[2]), "r"(a[3]), "r"(b0), "r"(b1));
}
__device__ __forceinline__ void ldsm4(uint32_t* r, uint32_t addr) {
    asm volatile("ldmatrix.sync.aligned.m8n8.x4.shared.b16 {%0,%1,%2,%3}, [%4];"
        : "=r"(r[0]), "=r"(r[1]), "=r"(r[2]), "=r"(r[3]) : "r"(addr));
}
__device__ __forceinline__ void ldsm4t(uint32_t* r, uint32_t addr) {
    asm volatile("ldmatrix.sync.aligned.m8n8.x4.trans.shared.b16 {%0,%1,%2,%3}, [%4];"
        : "=r"(r[0]), "=r"(r[1]), "=r"(r[2]), "=r"(r[3]) : "r"(addr));
}
__device__ __forceinline__ void cp16(uint32_t dst, const void* src) {
    asm volatile("cp.async.cg.shared.global [%0], [%1], 16;"
                 :: "r"(dst), "l"(src));
}
__device__ __forceinline__ void cp_commit() {
    asm volatile("cp.async.commit_group;" ::: "memory");
}
template <int N>
__device__ __forceinline__ void cp_wait() {
    asm volatile("cp.async.wait_group %0;" :: "n"(N) : "memory");
}
__device__ __forceinline__ uint32_t fh2(float a, float b) {
    __half2 h = __floats2half2_rn(a, b);
    return *(uint32_t*)&h;
}

// ===========================================================================
// elementwise fp32 -> fp16
// ===========================================================================
__global__ void cvt_f16_k(const float4* __restrict__ in,
                          __half2* __restrict__ out, int n4)
{
    int i = blockIdx.x * blockDim.x + threadIdx.x;
    if (i < n4) {
        float4 v = in[i];
        out[2*i]   = __floats2half2_rn(v.x, v.y);
        out[2*i+1] = __floats2half2_rn(v.z, v.w);
    }
}

// ===========================================================================
// transpose + convert: in [Kd][Nd] fp32 -> out [Nd][Kd] fp16
// ===========================================================================
__global__ void transpose_cvt_h(const float* __restrict__ in,
                                __half* __restrict__ out, int Kd, int Nd)
{
    __shared__ float tile[32][33];
    const int k0 = blockIdx.y * 32, n0 = blockIdx.x * 32;
    const int tx = threadIdx.x & 31, ty = threadIdx.x >> 5;
#pragma unroll
    for (int p = 0; p < 4; ++p) {
        int k = ty + p * 8;
        tile[k][tx] = in[(size_t)(k0 + k) * Nd + n0 + tx];
    }
    __syncthreads();
#pragma unroll
    for (int p = 0; p < 4; ++p) {
        int n = ty + p * 8;
        out[(size_t)(n0 + n) * Kd + k0 + tx] = __float2half_rn(tile[tx][n]);
    }
}

// ===========================================================================
// fp16 tensor-core GEMM, 3-stage cp.async pipeline + ldmatrix.
// R12-proven structure + SOFTWARE-PIPELINED FRAGMENTS in compute():
//   16 flattened (ks,jj) steps; B frags triple-buffered, prefetched 2 steps
//   (8 mma ~32cyc) ahead; A frags double-buffered, prefetched 1 ks ahead.
// Regs: acc 64 + af 16 + bf 12 ~= 92 (fits 128-reg / 2-CTA cap).
// F16OUT: store C as fp16 (for attention); else fp32.
// ===========================================================================
#define GEMM_SMEM_CP 98304

template <bool F16OUT>
__global__ __launch_bounds__(256, 2) void gemm_f16(
    const __half* __restrict__ A, const __half* __restrict__ BT,
    const float* __restrict__ bias, void* __restrict__ Cout,
    int M, int N, int K)
{
    extern __shared__ __align__(16) uint32_t sm4[];
    const uint32_t smem_base = smem_u32(sm4);
    const int tid  = threadIdx.x;
    const int lane = tid & 31;
    const int warp = tid >> 5;
    const int wm = warp & 3, wn = warp >> 2;
    const int m0 = blockIdx.y * 128, n0 = blockIdx.x * 128;
    const int NIT = K >> 6;   // BK=64

    float acc[2][8][4];
#pragma unroll
    for (int i = 0; i < 2; ++i)
#pragma unroll
        for (int j = 0; j < 8; ++j)
#pragma unroll
            for (int q = 0; q < 4; ++q) acc[i][j][q] = 0.f;

    auto issue = [&](int kt, int s) {
        const int k0 = kt << 6;
        const uint32_t ab = smem_base + (uint32_t)s * 16384;
#pragma unroll
        for (int p = 0; p < 4; ++p) {
            int i = tid + (p << 8);
            int r = i >> 3, u = i & 7;
            cp16(ab + (uint32_t)(r * 8 + (u ^ (r & 7))) * 16,
                 A + (size_t)(m0 + r) * K + k0 + (u << 3));
        }
        const uint32_t bb = smem_base + 49152u + (uint32_t)s * 16384;
#pragma unroll
        for (int p = 0; p < 4; ++p) {
            int i = tid + (p << 8);
            int r = i >> 3, u = i & 7;
            cp16(bb + (uint32_t)(r * 8 + (u ^ (r & 7))) * 16,
                 BT + (size_t)(n0 + r) * K + k0 + (u << 3));
        }
    };

    const int mlocA = lane & 15;
    const int khA   = lane >> 4;
    const int nlocB = (lane & 7) + ((lane >> 4) << 3);
    const int khB   = (lane >> 3) & 1;

    auto compute = [&](int st) {
        const uint32_t as_b = smem_base + (uint32_t)st * 16384;
        const uint32_t bs_b = smem_base + 49152u + (uint32_t)st * 16384;
        uint32_t af[2][2][4];   // [ks parity][i]
        uint32_t bf[3][4];      // step % 3

        auto ldA2 = [&](int ks, int pb) {
#pragma unroll
            for (int i = 0; i < 2; ++i) {
                int row = wm * 32 + i * 16 + mlocA;
                int unit = 2 * ks + khA;
                ldsm4(af[pb][i], as_b + (uint32_t)(row * 8 + (unit ^ (row & 7))) * 16);
            }
        };
        auto ldB1 = [&](int s2, int pb) {
            int ks = s2 >> 2, jj = s2 & 3;
            int row = wn * 64 + jj * 16 + nlocB;
            int unit = 2 * ks + khB;
            ldsm4(bf[pb], bs_b + (uint32_t)(row * 8 + (unit ^ (row & 7))) * 16);
        };

        ldA2(0, 0);
        ldB1(0, 0);
        ldB1(1, 1);
#pragma unroll
        for (int s2 = 0; s2 < 16; ++s2) {
            const int ks = s2 >> 2, jj = s2 & 3;
            if (s2 + 2 < 16) ldB1(s2 + 2, (s2 + 2) % 3);
            if (jj == 2 && ks < 3) ldA2(ks + 1, (ks + 1) & 1);
            const uint32_t* b = bf[s2 % 3];
            uint32_t (*a)[4] = af[ks & 1];
            mma_f16(acc[0][2*jj],   a[0], b[0], b[1]);
            mma_f16(acc[1][2*jj],   a[1], b[0], b[1]);
            mma_f16(acc[0][2*jj+1], a[0], b[2], b[3]);
            mma_f16(acc[1][2*jj+1], a[1], b[2], b[3]);
        }
    };

    issue(0, 0); cp_commit();
    issue(1, 1); cp_commit();
    for (int kt = 0; kt < NIT; ++kt) {
        cp_wait<1>();
        __syncthreads();
        compute(kt % 3);
        if (kt + 2 < NIT) issue(kt + 2, (kt + 2) % 3);
        cp_commit();
    }

#pragma unroll
    for (int i = 0; i < 2; ++i) {
        const int r = m0 + wm * 32 + i * 16 + (lane >> 2);
#pragma unroll
        for (int j = 0; j < 8; ++j) {
            const int c = n0 + wn * 64 + j * 8 + ((lane & 3) << 1);
            float2 bi = *(const float2*)&bias[c];
            float v00 = acc[i][j][0] + bi.x, v01 = acc[i][j][1] + bi.y;
            float v10 = acc[i][j][2] + bi.x, v11 = acc[i][j][3] + bi.y;
            if (F16OUT) {
                __half* Ch = (__half*)Cout;
                *(__half2*)&Ch[(size_t)r * N + c]       = __floats2half2_rn(v00, v01);
                *(__half2*)&Ch[(size_t)(r + 8) * N + c] = __floats2half2_rn(v10, v11);
            } else {
                float* Cc = (float*)Cout;
                *(float2*)&Cc[(size_t)r * N + c]       = make_float2(v00, v01);
                *(float2*)&Cc[(size_t)(r + 8) * N + c] = make_float2(v10, v11);
            }
        }
    }
}

// ===========================================================================
// fp16 tensor-core flash attention (causal) — R12-proven kernel, VERBATIM.
// ===========================================================================
#define ATTN_SMEM 69632   // 2 x (K 17408B + V 17408B); Q staging reuses K region

__global__ __launch_bounds__(256, 1) void attn_tc()
{
    extern __shared__ __align__(16) uint32_t smu[];
    const uint32_t smem_base = smem_u32(smu);

    const int tid  = threadIdx.x;
    const int lane = tid & 31;
    const int warp = tid >> 5;
    const int g = lane >> 2;
    const int t = lane & 3;
    const int qt = 7 - (int)blockIdx.x;
    const int b  = blockIdx.y >> 4, h = blockIdx.y & 15;

    const __half* seq = g_qkvh + (size_t)b * T_ * C3_ + h * D_;
    const __half* Qg = seq + (size_t)(qt * 128) * C3_;
    const __half* Kg = seq + C_;
    const __half* Vg = seq + 2 * C_;

#pragma unroll
    for (int p = 0; p < 8; ++p) {
        int i = tid + (p << 8);
        int r = i >> 4, u = i & 15;
        *(uint4*)&smu[r * 68 + u * 4] =
            *(const uint4*)(Qg + (size_t)r * C3_ + u * 8);
    }
    __syncthreads();

    uint32_t qf[8][4];
    {
        const int m = warp * 16 + g;
#pragma unroll
        for (int ks = 0; ks < 8; ++ks) {
            qf[ks][0] = smu[m * 68 + 8 * ks + t];
            qf[ks][1] = smu[(m + 8) * 68 + 8 * ks + t];
            qf[ks][2] = smu[m * 68 + 8 * ks + t + 4];
            qf[ks][3] = smu[(m + 8) * 68 + 8 * ks + t + 4];
        }
    }
    __syncthreads();

    float of[16][4];
#pragma unroll
    for (int nf = 0; nf < 16; ++nf)
#pragma unroll
        for (int q = 0; q < 4; ++q) of[nf][q] = 0.f;
    float m0h = -3.0e38f, m1h = -3.0e38f, l0 = 0.f, l1 = 0.f;

    const float scale = 0.08838834764831845f;
    const int rg0 = qt * 128 + warp * 16 + g;
    const int nt  = 2 * qt + 2;

    const int rowB = (lane & 7) + ((lane >> 4) << 3);
    const int colB = ((lane >> 3) & 1) * 8;
    const int rowV = (lane & 7) + (((lane >> 3) & 1) << 3);
    const int colV = (lane >> 4) * 8;

    auto issueKV = [&](int kt, int s) {
        const int kv0 = kt * 64;
        const uint32_t kb = smem_base + (uint32_t)s * 17408;
        const uint32_t vb = smem_base + 34816u + (uint32_t)s * 17408;
#pragma unroll
        for (int p = 0; p < 4; ++p) {
            int i = tid + (p << 8);
            int r = i >> 4, u = i & 15;
            cp16(kb + (uint32_t)(r * 272 + u * 16),
                 Kg + (size_t)(kv0 + r) * C3_ + u * 8);
            cp16(vb + (uint32_t)(r * 272 + u * 16),
                 Vg + (size_t)(kv0 + r) * C3_ + u * 8);
        }
    };

    issueKV(0, 0); cp_commit();

    for (int kt = 0; kt < nt; ++kt) {
        cp_wait<0>();
        __syncthreads();
        if (kt + 1 < nt) { issueKV(kt + 1, (kt + 1) & 1); cp_commit(); }

        const uint32_t kbase = smem_base + (uint32_t)(kt & 1) * 17408;
        const uint32_t vbase = smem_base + 34816u + (uint32_t)(kt & 1) * 17408;
        const int kv0 = kt * 64;

        float sc[8][4];
#pragma unroll
        for (int j = 0; j < 8; ++j)
#pragma unroll
            for (int q = 0; q < 4; ++q) sc[j][q] = 0.f;

#pragma unroll
        for (int ks = 0; ks < 8; ++ks) {
#pragma unroll
            for (int jj = 0; jj < 4; ++jj) {
                uint32_t bf[4];
                int row = jj * 16 + rowB;
                int colh = ks * 16 + colB;
                ldsm4(bf, kbase + (uint32_t)(row * 136 + colh) * 2);
                mma_f16(sc[2*jj],   qf[ks], bf[0], bf[1]);
                mma_f16(sc[2*jj+1], qf[ks], bf[2], bf[3]);
            }
        }

        {   // half 0
            float mt = -3.0e38f;
#pragma unroll
            for (int j = 0; j < 8; ++j) {
                int cg = kv0 + j * 8 + 2 * t;
                float v0 = sc[j][0] * scale; if (cg > rg0)     v0 = -1.0e9f;
                float v1 = sc[j][1] * scale; if (cg + 1 > rg0) v1 = -1.0e9f;
                sc[j][0] = v0; sc[j][1] = v1;
                mt = fmaxf(mt, fmaxf(v0, v1));
            }
            mt = fmaxf(mt, __shfl_xor_sync(~0u, mt, 1));
            mt = fmaxf(mt, __shfl_xor_sync(~0u, mt, 2));
            float mn = fmaxf(m0h, mt);
            float sum = 0.f;
#pragma unroll
            for (int j = 0; j < 8; ++j) {
                float p0 = __expf(sc[j][0] - mn);
                float p1 = __expf(sc[j][1] - mn);
                sum += p0 + p1;
                sc[j][0] = p0; sc[j][1] = p1;
            }
            sum += __shfl_xor_sync(~0u, sum, 1);
            sum += __shfl_xor_sync(~0u, sum, 2);
            float corr = __expf(m0h - mn);
            l0 = l0 * corr + sum; m0h = mn;
#pragma unroll
            for (int nf = 0; nf < 16; ++nf) { of[nf][0] *= corr; of[nf][1] *= corr; }
        }
        {   // half 1
            float mt = -3.0e38f;
#pragma unroll
            for (int j = 0; j < 8; ++j) {
                int cg = kv0 + j * 8 + 2 * t;
                float v0 = sc[j][2] * scale; if (cg > rg0 + 8)     v0 = -1.0e9f;
                float v1 = sc[j][3] * scale; if (cg + 1 > rg0 + 8) v1 = -1.0e9f;
                sc[j][2] = v0; sc[j][3] = v1;
                mt = fmaxf(mt, fmaxf(v0, v1));
            }
            mt = fmaxf(mt, __shfl_xor_sync(~0u, mt, 1));
            mt = fmaxf(mt, __shfl_xor_sync(~0u, mt, 2));
            float mn = fmaxf(m1h, mt);
            float sum = 0.f;
#pragma unroll
            for (int j = 0; j < 8; ++j) {
                float p0 = __expf(sc[j][2] - mn);
                float p1 = __expf(sc[j][3] - mn);
                sum += p0 + p1;
                sc[j][2] = p0; sc[j][3] = p1;
            }
            sum += __shfl_xor_sync(~0u, sum, 1);
            sum += __shfl_xor_sync(~0u, sum, 2);
            float corr = __expf(m1h - mn);
            l1 = l1 * corr + sum; m1h = mn;
#pragma unroll
            for (int nf = 0; nf < 16; ++nf) { of[nf][2] *= corr; of[nf][3] *= corr; }
        }

        uint32_t pa[4][4];
#pragma unroll
        for (int ks2 = 0; ks2 < 4; ++ks2) {
            pa[ks2][0] = fh2(sc[2*ks2][0],   sc[2*ks2][1]);
            pa[ks2][1] = fh2(sc[2*ks2][2],   sc[2*ks2][3]);
            pa[ks2][2] = fh2(sc[2*ks2+1][0], sc[2*ks2+1][1]);
            pa[ks2][3] = fh2(sc[2*ks2+1][2], sc[2*ks2+1][3]);
        }

#pragma unroll
        for (int ks2 = 0; ks2 < 4; ++ks2) {
#pragma unroll
            for (int nn = 0; nn < 8; ++nn) {
                uint32_t bf[4];
                int row = ks2 * 16 + rowV;
                int cold = nn * 16 + colV;
                ldsm4t(bf, vbase + (uint32_t)(row * 136 + cold) * 2);
                mma_f16(of[2*nn],   pa[ks2], bf[0], bf[1]);
                mma_f16(of[2*nn+1], pa[ks2], bf[2], bf[3]);
            }
        }
    }

    const float inv0 = 1.0f / l0, inv1 = 1.0f / l1;
    const size_t r0 = (size_t)(b*T_ + qt*128 + warp*16 + g) * C_ + h*D_;
#pragma unroll
    for (int nf = 0; nf < 16; ++nf) {
        const int col = nf * 8 + 2 * t;
        *(__half2*)&g_yh[r0 + col] =
            __floats2half2_rn(of[nf][0] * inv0, of[nf][1] * inv0);
        *(__half2*)&g_yh[r0 + (size_t)8 * C_ + col] =
            __floats2half2_rn(of[nf][2] * inv1, of[nf][3] * inv1);
    }
}

// ---------------------------------------------------------------------------
extern "C" void kernel_launch(void* const* d_in, const int* in_sizes, int n_in,
                              void* d_out, int out_size)
{
    const float* x      = (const float*)d_in[0];
    const float* W_attn = (const float*)d_in[1];
    const float* b_attn = (const float*)d_in[2];
    const float* W_proj = (const float*)d_in[3];
    const float* b_proj = (const float*)d_in[4];
    float* out = (float*)d_out;

    __half *qkvh = nullptr, *xh = nullptr, *wath = nullptr,
           *wpth = nullptr, *yh = nullptr;
    cudaGetSymbolAddress((void**)&qkvh, g_qkvh);
    cudaGetSymbolAddress((void**)&xh,   g_xh);
    cudaGetSymbolAddress((void**)&wath, g_wath);
    cudaGetSymbolAddress((void**)&wpth, g_wpth);
    cudaGetSymbolAddress((void**)&yh,   g_yh);

    cudaFuncSetAttribute(gemm_f16<true>,
                         cudaFuncAttributeMaxDynamicSharedMemorySize, GEMM_SMEM_CP);
    cudaFuncSetAttribute(gemm_f16<false>,
                         cudaFuncAttributeMaxDynamicSharedMemorySize, GEMM_SMEM_CP);
    cudaFuncSetAttribute(attn_tc,
                         cudaFuncAttributeMaxDynamicSharedMemorySize, ATTN_SMEM);

    // 0) one-shot conversions: x -> fp16 row-major, W -> fp16 TRANSPOSED [N][K]
    int n4 = (B_*T_*C_) / 4;
    cvt_f16_k<<<(n4 + 255) / 256, 256>>>((const float4*)x, (__half2*)xh, n4);
    transpose_cvt_h<<<dim3(C3_/32, C_/32), 256>>>(W_attn, wath, C_, C3_);
    transpose_cvt_h<<<dim3(C_/32,  C_/32), 256>>>(W_proj, wpth, C_, C_);

    // 1) qkv = x @ W_attn + b_attn -> fp16        [8192, 6144]
    gemm_f16<true><<<dim3(C3_/128, (B_*T_)/128), 256, GEMM_SMEM_CP>>>(
        xh, wath, b_attn, qkvh, B_*T_, C3_, C_);

    // 2) causal flash attention -> g_yh (fp16)    [8192, 2048]
    attn_tc<<<dim3(T_/128, B_*H_), 256, ATTN_SMEM>>>();

    // 3) out = y @ W_proj + b_proj                [8192, 2048]
    gemm_f16<false><<<dim3(C_/128, (B_*T_)/128), 256, GEMM_SMEM_CP>>>(
        yh, wpth, b_proj, out, B_*T_, C_, C_);
}